// round 13
// baseline (speedup 1.0000x reference)
#include <cuda_runtime.h>
#include <cuda_bf16.h>
#include <cstdint>
#include <math.h>

#define NN 50000
#define NE 800000
#define NE2 850000
#define SCAN_BS 512
#define SCAN_NB ((NN + SCAN_BS - 1) / SCAN_BS)

// ---------------- device scratch ----------------
__device__ __align__(16) float g_x1[(size_t)NN * 256];
__device__ __align__(16) float g_x2[(size_t)NN * 128];
__device__ __align__(16) float g_A [(size_t)NN * 256];
__device__ __align__(16) float g_B [(size_t)NN * 256];
__device__ __align__(16) float g_C [(size_t)NN * 256];
__device__ __align__(16) float g_D [(size_t)NN * 128];
__device__ float    g_dinv[NN];
__device__ int      g_src[NE];
__device__ int      g_dst[NE];
__device__ int      g_cnt[NN];
__device__ int      g_off[NN + 1];
__device__ int      g_cur[NN];
__device__ int      g_bsum[SCAN_NB + 32];
__device__ int      g_csr_s[NE2];
__device__ float    g_csr_w[NE2];
__device__ int      g_eflag[1];
__device__ __align__(16) __nv_bfloat16 g_wt[600000];

static inline int divup(long long a, int b) { return (int)((a + b - 1) / b); }

// ---------------- PTX helpers (plain-sm_100 legal) ----------------
__device__ __forceinline__ uint32_t smem_u32(const void* p) {
    uint32_t a;
    asm("{ .reg .u64 t; cvta.to.shared.u64 t, %1; cvt.u32.u64 %0, t; }" : "=r"(a) : "l"(p));
    return a;
}
__device__ __forceinline__ void ldm_x4(uint32_t (&r)[4], uint32_t addr) {
    asm volatile("ldmatrix.sync.aligned.m8n8.x4.shared.b16 {%0,%1,%2,%3}, [%4];"
                 : "=r"(r[0]), "=r"(r[1]), "=r"(r[2]), "=r"(r[3]) : "r"(addr));
}
__device__ __forceinline__ void mma16816(float (&d)[4], const uint32_t (&a)[4],
                                         uint32_t b0, uint32_t b1) {
    asm volatile(
        "mma.sync.aligned.m16n8k16.row.col.f32.bf16.bf16.f32 "
        "{%0,%1,%2,%3}, {%4,%5,%6,%7}, {%8,%9}, {%0,%1,%2,%3};"
        : "+f"(d[0]), "+f"(d[1]), "+f"(d[2]), "+f"(d[3])
        : "r"(a[0]), "r"(a[1]), "r"(a[2]), "r"(a[3]), "r"(b0), "r"(b1));
}
__device__ __forceinline__ void cp_async16(uint32_t dst, const void* src, int szw) {
    asm volatile("cp.async.cg.shared.global [%0], [%1], 16, %2;"
                 :: "r"(dst), "l"(src), "r"(szw) : "memory");
}
__device__ __forceinline__ void cp_commit() { asm volatile("cp.async.commit_group;" ::: "memory"); }
__device__ __forceinline__ void cp_wait0()  { asm volatile("cp.async.wait_group 0;" ::: "memory"); }

// ---------------- edge-index dtype detection + conversion ----------------
__global__ void k_detect(const int* __restrict__ ei32) {
    __shared__ int cnt;
    if (threadIdx.x == 0) cnt = 0;
    __syncthreads();
    int nz = 0;
    for (int i = threadIdx.x; i < 2048; i += blockDim.x)
        if (ei32[2 * i + 1] != 0) nz++;
    atomicAdd(&cnt, nz);
    __syncthreads();
    if (threadIdx.x == 0) g_eflag[0] = (cnt == 0) ? 1 : 0;
}
__global__ void k_convert(const int* __restrict__ ei32,
                          int* __restrict__ src, int* __restrict__ dst) {
    int e = blockIdx.x * blockDim.x + threadIdx.x;
    if (e >= NE) return;
    int is64 = g_eflag[0];
    int s, d;
    if (is64) { s = ei32[2 * e]; d = ei32[2 * (NE + e)]; }
    else      { s = ei32[e];     d = ei32[NE + e]; }
    s = min(max(s, 0), NN - 1);
    d = min(max(d, 0), NN - 1);
    src[e] = s; dst[e] = d;
}

// ---------------- weight pre-transpose + bf16 split ----------------
__global__ void k_splitw(const float* __restrict__ W, __nv_bfloat16* __restrict__ wt,
                         int m, int k, int mpad) {
    int idx = blockIdx.x * blockDim.x + threadIdx.x;
    int tot = k * mpad;
    if (idx >= tot) return;
    int j = idx / mpad, kk = idx % mpad;
    float f = (kk < m) ? W[(size_t)kk * k + j] : 0.0f;
    __nv_bfloat16 h = __float2bfloat16(f);
    __nv_bfloat16 l = __float2bfloat16(f - __bfloat162float(h));
    wt[idx] = h;
    wt[tot + idx] = l;
}

// ---------------- CSR build ----------------
__global__ void k_fill_i(int* p, int n, int v) {
    int i = blockIdx.x * blockDim.x + threadIdx.x;
    if (i < n) p[i] = v;
}
__global__ void k_count(const int* __restrict__ dst, int* __restrict__ cnt) {
    int e = blockIdx.x * blockDim.x + threadIdx.x;
    if (e < NE) atomicAdd(&cnt[dst[e]], 1);
}
__global__ void k_dinv(const int* __restrict__ cnt, float* __restrict__ dinv) {
    int i = blockIdx.x * blockDim.x + threadIdx.x;
    if (i < NN) dinv[i] = rsqrtf((float)cnt[i]);
}
__global__ void scan1(const int* __restrict__ cnt, int* __restrict__ bsum) {
    __shared__ int sh[SCAN_BS];
    int i = blockIdx.x * SCAN_BS + threadIdx.x;
    sh[threadIdx.x] = (i < NN) ? cnt[i] : 0;
    __syncthreads();
    for (int s = SCAN_BS / 2; s; s >>= 1) {
        if (threadIdx.x < s) sh[threadIdx.x] += sh[threadIdx.x + s];
        __syncthreads();
    }
    if (threadIdx.x == 0) bsum[blockIdx.x] = sh[0];
}
__global__ void scan2(int* __restrict__ bsum) {
    __shared__ int sh[1024];
    int v = (threadIdx.x < SCAN_NB) ? bsum[threadIdx.x] : 0;
    sh[threadIdx.x] = v;
    __syncthreads();
    for (int o = 1; o < 1024; o <<= 1) {
        int t = (threadIdx.x >= o) ? sh[threadIdx.x - o] : 0;
        __syncthreads();
        sh[threadIdx.x] += t;
        __syncthreads();
    }
    if (threadIdx.x < SCAN_NB) bsum[threadIdx.x] = sh[threadIdx.x] - v;
}
__global__ void scan3(const int* __restrict__ cnt, const int* __restrict__ bsum,
                      int* __restrict__ off) {
    __shared__ int sh[SCAN_BS];
    int i = blockIdx.x * SCAN_BS + threadIdx.x;
    int v = (i < NN) ? cnt[i] : 0;
    sh[threadIdx.x] = v;
    __syncthreads();
    for (int o = 1; o < SCAN_BS; o <<= 1) {
        int t = (threadIdx.x >= o) ? sh[threadIdx.x - o] : 0;
        __syncthreads();
        sh[threadIdx.x] += t;
        __syncthreads();
    }
    if (i <= NN) off[i] = bsum[blockIdx.x] + sh[threadIdx.x] - v;
}
__global__ void k_copy_i(const int* __restrict__ a, int* __restrict__ b, int n) {
    int i = blockIdx.x * blockDim.x + threadIdx.x;
    if (i < n) b[i] = a[i];
}
__global__ void k_bucket(const int* __restrict__ src, const int* __restrict__ dst,
                         const float* __restrict__ dinv, int* __restrict__ cur,
                         int* __restrict__ cs, float* __restrict__ cw) {
    int t = blockIdx.x * blockDim.x + threadIdx.x;
    if (t >= NE2) return;
    int s, d;
    if (t < NE) { s = src[t]; d = dst[t]; }
    else        { s = d = t - NE; }
    int pos = atomicAdd(&cur[d], 1);
    cs[pos] = s;
    cw[pos] = dinv[s] * dinv[d];
}

// ---------------- mma.sync bf16x3 GEMM, 2-stage pipeline (dynamic smem) ----------------
// Block 128x128, 8 warps (4 M x 2 N), warp tile 32x64, K-tile 32 (2 x k16).
// Dynamic smem layout (byte offsets, BUFSZ=10240 each):
//   Ah0 Ah1 Al0 Al1 Bh0 Bh1 Bl0 Bl1  -> total 81920 B
// EPI: 0 none, 1 GCN2 relu((1-b)A + b*AW) (m==k), 2 relu(AW + bias)
#define LDS_B 80
#define BUFSZ (128 * LDS_B)
#define GSMEM (8 * BUFSZ)
template <int EPI>
__global__ __launch_bounds__(256) void gemm_mma(
    const float* __restrict__ A, const __nv_bfloat16* __restrict__ Wt,
    float* __restrict__ C, int n, int m, int k, int mpad, float beta,
    const float* __restrict__ bias) {
    extern __shared__ __align__(16) char smem[];
    char* sAh = smem;                 // [2][BUFSZ]
    char* sAl = smem + 2 * BUFSZ;
    char* sBh = smem + 4 * BUFSZ;
    char* sBl = smem + 6 * BUFSZ;

    const int tid  = threadIdx.x;
    const int wid  = tid >> 5, lane = tid & 31;
    const int warp_m = wid & 3, warp_n = wid >> 2;
    const int row0 = blockIdx.y * 128;
    const int col0 = blockIdx.x * 128;
    const int planeoff = k * mpad;

    const uint32_t ah_b = smem_u32(sAh), al_b = smem_u32(sAl);
    const uint32_t bh_b = smem_u32(sBh), bl_b = smem_u32(sBl);
    const int lr = lane & 15, lc = lane >> 4;
    const uint32_t a_off = (uint32_t)(warp_m * 32 + lr) * LDS_B + lc * 16;
    const uint32_t b_off = (uint32_t)(warp_n * 64 + lr) * LDS_B + lc * 16;

    int a_r[4], a_q[4];
    #pragma unroll
    for (int i = 0; i < 4; i++) {
        int idx = tid + i * 256;
        a_r[i] = idx >> 3;
        a_q[i] = idx & 7;
    }
    int b_j[2], b_kq[2];
    #pragma unroll
    for (int i = 0; i < 2; i++) {
        int idx = tid + i * 256;
        b_j[i] = idx >> 2;
        b_kq[i] = idx & 3;
    }

    float acc[2][8][4];
    #pragma unroll
    for (int i = 0; i < 2; i++)
        #pragma unroll
        for (int j = 0; j < 8; j++)
            #pragma unroll
            for (int r = 0; r < 4; r++) acc[i][j][r] = 0.0f;

    const float4 ZF = make_float4(0.f, 0.f, 0.f, 0.f);
    const int nt = mpad / 32;

    auto issue_B = [&](int t, int b) {
        #pragma unroll
        for (int i = 0; i < 2; i++) {
            int gj = col0 + b_j[i];
            int ok = (gj < k) ? 16 : 0;
            size_t g = (size_t)((gj < k) ? gj : 0) * mpad + t * 32 + b_kq[i] * 8;
            uint32_t so = (uint32_t)(b_j[i] * LDS_B + b_kq[i] * 16);
            cp_async16(bh_b + b * BUFSZ + so, &Wt[g], ok);
            cp_async16(bl_b + b * BUFSZ + so, &Wt[planeoff + g], ok);
        }
        cp_commit();
    };
    auto load_A = [&](int t, float4 (&pa)[4]) {
        #pragma unroll
        for (int i = 0; i < 4; i++) {
            int gr = row0 + a_r[i], gk = t * 32 + a_q[i] * 4;
            pa[i] = (gr < n && gk < m) ? *(const float4*)&A[(size_t)gr * m + gk] : ZF;
        }
    };
    auto store_A = [&](const float4 (&pa)[4], int b) {
        #pragma unroll
        for (int i = 0; i < 4; i++) {
            float4 v = pa[i];
            __nv_bfloat16 h0 = __float2bfloat16(v.x), h1 = __float2bfloat16(v.y);
            __nv_bfloat16 h2 = __float2bfloat16(v.z), h3 = __float2bfloat16(v.w);
            __nv_bfloat16 l0 = __float2bfloat16(v.x - __bfloat162float(h0));
            __nv_bfloat16 l1 = __float2bfloat16(v.y - __bfloat162float(h1));
            __nv_bfloat16 l2 = __float2bfloat16(v.z - __bfloat162float(h2));
            __nv_bfloat16 l3 = __float2bfloat16(v.w - __bfloat162float(h3));
            __nv_bfloat162 hp0 = {h0, h1}, hp1 = {h2, h3};
            __nv_bfloat162 lp0 = {l0, l1}, lp1 = {l2, l3};
            uint2 uh = make_uint2(*(uint32_t*)&hp0, *(uint32_t*)&hp1);
            uint2 ul = make_uint2(*(uint32_t*)&lp0, *(uint32_t*)&lp1);
            *(uint2*)(sAh + b * BUFSZ + a_r[i] * LDS_B + a_q[i] * 8) = uh;
            *(uint2*)(sAl + b * BUFSZ + a_r[i] * LDS_B + a_q[i] * 8) = ul;
        }
    };

    // prologue: tile 0 -> buf 0
    {
        float4 pa[4];
        issue_B(0, 0);
        load_A(0, pa);
        store_A(pa, 0);
        cp_wait0();
        __syncthreads();
    }

    for (int t = 0; t < nt; t++) {
        const int buf = t & 1;
        float4 pa[4];
        if (t + 1 < nt) {
            issue_B(t + 1, buf ^ 1);
            load_A(t + 1, pa);
        }
        const uint32_t abase  = ah_b + buf * BUFSZ + a_off;
        const uint32_t albase = al_b + buf * BUFSZ + a_off;
        const uint32_t bbase  = bh_b + buf * BUFSZ + b_off;
        const uint32_t blbase = bl_b + buf * BUFSZ + b_off;
        #pragma unroll
        for (int ks = 0; ks < 2; ks++) {
            const uint32_t kb2 = ks * 32;
            uint32_t ah[2][4], al[2][4], bh[4][4], bl[4][4];
            #pragma unroll
            for (int mt = 0; mt < 2; mt++) {
                ldm_x4(ah[mt], abase + mt * (16 * LDS_B) + kb2);
                ldm_x4(al[mt], albase + mt * (16 * LDS_B) + kb2);
            }
            #pragma unroll
            for (int nt2 = 0; nt2 < 4; nt2++) {
                ldm_x4(bh[nt2], bbase + nt2 * (16 * LDS_B) + kb2);
                ldm_x4(bl[nt2], blbase + nt2 * (16 * LDS_B) + kb2);
            }
            #pragma unroll
            for (int mt = 0; mt < 2; mt++)
                #pragma unroll
                for (int nt2 = 0; nt2 < 4; nt2++) {
                    mma16816(acc[mt][nt2*2+0], ah[mt], bh[nt2][0], bh[nt2][2]);
                    mma16816(acc[mt][nt2*2+1], ah[mt], bh[nt2][1], bh[nt2][3]);
                    mma16816(acc[mt][nt2*2+0], ah[mt], bl[nt2][0], bl[nt2][2]);
                    mma16816(acc[mt][nt2*2+1], ah[mt], bl[nt2][1], bl[nt2][3]);
                    mma16816(acc[mt][nt2*2+0], al[mt], bh[nt2][0], bh[nt2][2]);
                    mma16816(acc[mt][nt2*2+1], al[mt], bh[nt2][1], bh[nt2][3]);
                }
        }
        if (t + 1 < nt) {
            store_A(pa, buf ^ 1);
            cp_wait0();
        }
        __syncthreads();
    }

    // ---- epilogue ----
    const int g = lane >> 2, t = lane & 3;
    #pragma unroll
    for (int mt = 0; mt < 2; mt++) {
        #pragma unroll
        for (int ntg = 0; ntg < 8; ntg++) {
            int gc = col0 + warp_n * 64 + ntg * 8 + t * 2;
            if (gc >= k) continue;
            #pragma unroll
            for (int half = 0; half < 2; half++) {
                int gr = row0 + warp_m * 32 + mt * 16 + g + half * 8;
                if (gr >= n) continue;
                float c0 = acc[mt][ntg][half * 2 + 0];
                float c1 = acc[mt][ntg][half * 2 + 1];
                if (EPI == 1) {
                    float2 x0 = *(const float2*)&A[(size_t)gr * m + gc];
                    c0 = fmaxf(beta * c0 + (1.0f - beta) * x0.x, 0.f);
                    c1 = fmaxf(beta * c1 + (1.0f - beta) * x0.y, 0.f);
                } else if (EPI == 2) {
                    float2 b = *(const float2*)&bias[gc];
                    c0 = fmaxf(c0 + b.x, 0.f);
                    c1 = fmaxf(c1 + b.y, 0.f);
                }
                *(float2*)&C[(size_t)gr * k + gc] = make_float2(c0, c1);
            }
        }
    }
}

// ---------------- pull-based GCN propagation (unroll 4) ----------------
template <int D4, int MODE>
__global__ void prop_pull(const float4* __restrict__ h, float4* __restrict__ o,
                          const float* __restrict__ aux,
                          const int* __restrict__ off, const int* __restrict__ csr_s,
                          const float* __restrict__ csr_w) {
    constexpr int TPN = (D4 < 32) ? D4 : 32;
    constexpr int NPW = 32 / TPN;
    constexpr int R   = D4 / TPN;
    int gwarp = (blockIdx.x * blockDim.x + threadIdx.x) >> 5;
    int lane  = threadIdx.x & 31;
    int node  = gwarp * NPW + lane / TPN;
    int tl    = lane % TPN;
    if (node >= NN) return;

    float4 acc[R];
    #pragma unroll
    for (int r = 0; r < R; r++) acc[r] = make_float4(0.f, 0.f, 0.f, 0.f);

    int j0 = off[node], j1 = off[node + 1];
    int j = j0;
    for (; j + 3 < j1; j += 4) {
        int   s0 = csr_s[j],   s1 = csr_s[j+1], s2 = csr_s[j+2], s3 = csr_s[j+3];
        float w0 = csr_w[j],   w1 = csr_w[j+1], w2 = csr_w[j+2], w3 = csr_w[j+3];
        #pragma unroll
        for (int r = 0; r < R; r++) {
            float4 v0 = h[(size_t)s0 * D4 + tl + r * TPN];
            float4 v1 = h[(size_t)s1 * D4 + tl + r * TPN];
            float4 v2 = h[(size_t)s2 * D4 + tl + r * TPN];
            float4 v3 = h[(size_t)s3 * D4 + tl + r * TPN];
            acc[r].x += w0*v0.x + w1*v1.x + w2*v2.x + w3*v3.x;
            acc[r].y += w0*v0.y + w1*v1.y + w2*v2.y + w3*v3.y;
            acc[r].z += w0*v0.z + w1*v1.z + w2*v2.z + w3*v3.z;
            acc[r].w += w0*v0.w + w1*v1.w + w2*v2.w + w3*v3.w;
        }
    }
    for (; j < j1; j++) {
        int s0 = csr_s[j];
        float w0 = csr_w[j];
        #pragma unroll
        for (int r = 0; r < R; r++) {
            float4 v0 = h[(size_t)s0 * D4 + tl + r * TPN];
            acc[r].x += w0 * v0.x; acc[r].y += w0 * v0.y;
            acc[r].z += w0 * v0.z; acc[r].w += w0 * v0.w;
        }
    }

    const float4* aux4 = (const float4*)aux;
    #pragma unroll
    for (int r = 0; r < R; r++) {
        int c = tl + r * TPN;
        float4 v = acc[r];
        if (MODE == 0 || MODE == 2) {
            float4 b = aux4[c];
            v.x += b.x; v.y += b.y; v.z += b.z; v.w += b.w;
            if (MODE == 0) {
                v.x = fmaxf(v.x, 0.f); v.y = fmaxf(v.y, 0.f);
                v.z = fmaxf(v.z, 0.f); v.w = fmaxf(v.w, 0.f);
            }
        } else if (MODE == 1) {
            float4 x0 = aux4[(size_t)node * D4 + c];
            v.x = 0.5f * (v.x + x0.x); v.y = 0.5f * (v.y + x0.y);
            v.z = 0.5f * (v.z + x0.z); v.w = 0.5f * (v.w + x0.w);
        }
        o[(size_t)node * D4 + c] = v;
    }
}

// ---------------- GATv2: fused flash-softmax ----------------
__global__ void gat_fused(const float4* __restrict__ xl4, const float4* __restrict__ xr4,
                          const int* __restrict__ off, const int* __restrict__ cs,
                          const float4* __restrict__ att4, const float* __restrict__ bg,
                          float4* __restrict__ out) {
    int node = (blockIdx.x * blockDim.x + threadIdx.x) >> 5;
    int lane = threadIdx.x & 31;
    if (node >= NN) return;
    int j0 = off[node], j1 = off[node + 1];

    float4 xr = xr4[(size_t)node * 32 + lane];
    float4 at = att4[lane];

    float m = -1e30f, s = 0.0f;
    float4 acc = make_float4(0.f, 0.f, 0.f, 0.f);

    for (int j = j0; j < j1; j++) {
        int sn = cs[j];
        float4 v = xl4[(size_t)sn * 32 + lane];
        float e0 = v.x + xr.x; e0 = (e0 > 0.f) ? e0 : 0.2f * e0;
        float e1 = v.y + xr.y; e1 = (e1 > 0.f) ? e1 : 0.2f * e1;
        float e2 = v.z + xr.z; e2 = (e2 > 0.f) ? e2 : 0.2f * e2;
        float e3 = v.w + xr.w; e3 = (e3 > 0.f) ? e3 : 0.2f * e3;
        float p = e0 * at.x + e1 * at.y + e2 * at.z + e3 * at.w;
        p += __shfl_xor_sync(0xffffffffu, p, 1);
        p += __shfl_xor_sync(0xffffffffu, p, 2);
        p += __shfl_xor_sync(0xffffffffu, p, 4);
        float nm = fmaxf(m, p);
        float r  = __expf(m - nm);
        float w  = __expf(p - nm);
        s = s * r + w;
        acc.x = acc.x * r + w * v.x;
        acc.y = acc.y * r + w * v.y;
        acc.z = acc.z * r + w * v.z;
        acc.w = acc.w * r + w * v.w;
        m = nm;
    }
    float inv = 1.0f / (s + 1e-16f);
    float4 b = ((const float4*)bg)[lane];
    acc.x = fmaxf(acc.x * inv + b.x, 0.f);
    acc.y = fmaxf(acc.y * inv + b.y, 0.f);
    acc.z = fmaxf(acc.z * inv + b.z, 0.f);
    acc.w = fmaxf(acc.w * inv + b.w, 0.f);
    out[(size_t)node * 32 + lane] = acc;
}

// ---------------- host helpers ----------------
static inline int mpad32(int m) { return ((m + 31) / 32) * 32; }

static void gemm(const float* A, const __nv_bfloat16* Wt, float* C,
                 int n, int m, int k, int epi, float beta, const float* bias,
                 cudaStream_t st) {
    int mp = mpad32(m);
    dim3 grid(divup(k, 128), divup(n, 128));
    if (epi == 1)      gemm_mma<1><<<grid, 256, GSMEM, st>>>(A, Wt, C, n, m, k, mp, beta, nullptr);
    else if (epi == 2) gemm_mma<2><<<grid, 256, GSMEM, st>>>(A, Wt, C, n, m, k, mp, 0.0f, bias);
    else               gemm_mma<0><<<grid, 256, GSMEM, st>>>(A, Wt, C, n, m, k, mp, 0.0f, nullptr);
}

template <int D4, int MODE>
static void prop_launch(const float* h, float* o, const float* aux,
                        const int* off, const int* cs, const float* cw) {
    constexpr int NPW = (D4 < 32) ? (32 / D4) : 1;
    int warps = divup(NN, NPW);
    prop_pull<D4, MODE><<<divup((long long)warps * 32, 256), 256>>>(
        (const float4*)h, (float4*)o, aux, off, cs, cw);
}

static cudaStream_t s_side = nullptr;
static cudaEvent_t  s_ev0, s_ev1, s_ev2, s_ev3;

#define WOFF_W1  0
#define WOFF_W2  (WOFF_W1  + 2 * 256 * 320)
#define WOFF_W3  (WOFF_W2  + 2 * 128 * 256)
#define WOFF_W4  (WOFF_W3  + 2 * 64 * 128)
#define WOFF_WL  (WOFF_W4  + 2 * 32 * 64)
#define WOFF_WR  (WOFF_WL  + 2 * 128 * 32)
#define WOFF_WC1 (WOFF_WR  + 2 * 128 * 32)
#define WOFF_W5  (WOFF_WC1 + 2 * 128 * 128)
#define WOFF_WC2 (WOFF_W5  + 2 * 256 * 128)
#define WOFF_WO  (WOFF_WC2 + 2 * 256 * 256)

extern "C" void kernel_launch(void* const* d_in, const int* in_sizes, int n_in,
                              void* d_out, int out_size) {
    if (!s_side) {
        cudaStreamCreateWithFlags(&s_side, cudaStreamNonBlocking);
        cudaEventCreateWithFlags(&s_ev0, cudaEventDisableTiming);
        cudaEventCreateWithFlags(&s_ev1, cudaEventDisableTiming);
        cudaEventCreateWithFlags(&s_ev2, cudaEventDisableTiming);
        cudaEventCreateWithFlags(&s_ev3, cudaEventDisableTiming);
        cudaFuncSetAttribute(gemm_mma<0>, cudaFuncAttributeMaxDynamicSharedMemorySize, GSMEM);
        cudaFuncSetAttribute(gemm_mma<1>, cudaFuncAttributeMaxDynamicSharedMemorySize, GSMEM);
        cudaFuncSetAttribute(gemm_mma<2>, cudaFuncAttributeMaxDynamicSharedMemorySize, GSMEM);
    }
    const cudaStream_t MAIN = 0;

    const float* x   = (const float*)d_in[0];
    const int*   ei32= (const int*)d_in[1];
    const float* W1 = (const float*)d_in[2];  const float* b1 = (const float*)d_in[3];
    const float* W2 = (const float*)d_in[4];  const float* b2 = (const float*)d_in[5];
    const float* W3 = (const float*)d_in[6];  const float* b3 = (const float*)d_in[7];
    const float* W4 = (const float*)d_in[8];  const float* b4 = (const float*)d_in[9];
    const float* Wl = (const float*)d_in[10]; const float* Wr = (const float*)d_in[11];
    const float* att= (const float*)d_in[12]; const float* bg = (const float*)d_in[13];
    const float* Wc1= (const float*)d_in[14];
    const float* W5 = (const float*)d_in[15]; const float* b5 = (const float*)d_in[16];
    const float* Wc2= (const float*)d_in[17];
    const float* Wo = (const float*)d_in[18]; const float* bo = (const float*)d_in[19];
    float* out = (float*)d_out;

    float *x1, *x2, *A, *B, *C, *D, *dinv, *cw;
    int *src, *dst, *cnt, *off, *cur, *bsum, *cs;
    __nv_bfloat16* wt;
    cudaGetSymbolAddress((void**)&x1,   g_x1);
    cudaGetSymbolAddress((void**)&x2,   g_x2);
    cudaGetSymbolAddress((void**)&A,    g_A);
    cudaGetSymbolAddress((void**)&B,    g_B);
    cudaGetSymbolAddress((void**)&C,    g_C);
    cudaGetSymbolAddress((void**)&D,    g_D);
    cudaGetSymbolAddress((void**)&dinv, g_dinv);
    cudaGetSymbolAddress((void**)&src,  g_src);
    cudaGetSymbolAddress((void**)&dst,  g_dst);
    cudaGetSymbolAddress((void**)&cnt,  g_cnt);
    cudaGetSymbolAddress((void**)&off,  g_off);
    cudaGetSymbolAddress((void**)&cur,  g_cur);
    cudaGetSymbolAddress((void**)&bsum, g_bsum);
    cudaGetSymbolAddress((void**)&cs,   g_csr_s);
    cudaGetSymbolAddress((void**)&cw,   g_csr_w);
    cudaGetSymbolAddress((void**)&wt,   g_wt);

    const float BETA = logf(1.05f);

    // ---- head: detect(1), convert(2), splitW1(3), gemm1(4 <- profiled) ----
    k_detect<<<1, 256>>>(ei32);
    k_convert<<<divup(NE, 256), 256>>>(ei32, src, dst);
    k_splitw<<<divup(256 * 320, 256), 256>>>(W1, wt + WOFF_W1, 300, 256, 320);
    gemm(x, wt + WOFF_W1, A, NN, 300, 256, 0, 0.0f, nullptr, MAIN);
    cudaEventRecord(s_ev0, MAIN);
    cudaStreamWaitEvent(s_side, s_ev0, 0);

    // side stream: remaining weight splits + CSR build
    k_splitw<<<divup(128 * 256, 256), 256, 0, s_side>>>(W2,  wt + WOFF_W2,  256, 128, 256);
    k_splitw<<<divup(64 * 128, 256),  256, 0, s_side>>>(W3,  wt + WOFF_W3,  128, 64, 128);
    k_splitw<<<divup(32 * 64, 256),   256, 0, s_side>>>(W4,  wt + WOFF_W4,  64, 32, 64);
    k_splitw<<<divup(128 * 32, 256),  256, 0, s_side>>>(Wl,  wt + WOFF_WL,  32, 128, 32);
    k_splitw<<<divup(128 * 32, 256),  256, 0, s_side>>>(Wr,  wt + WOFF_WR,  32, 128, 32);
    k_splitw<<<divup(128 * 128, 256), 256, 0, s_side>>>(Wc1, wt + WOFF_WC1, 128, 128, 128);
    k_splitw<<<divup(256 * 128, 256), 256, 0, s_side>>>(W5,  wt + WOFF_W5,  128, 256, 128);
    k_splitw<<<divup(256 * 256, 256), 256, 0, s_side>>>(Wc2, wt + WOFF_WC2, 256, 256, 256);
    k_splitw<<<divup(128 * 256, 256), 256, 0, s_side>>>(Wo,  wt + WOFF_WO,  256, 128, 256);
    k_fill_i<<<divup(NN, 256), 256, 0, s_side>>>(cnt, NN, 1);
    k_count<<<divup(NE, 256), 256, 0, s_side>>>(dst, cnt);
    k_dinv<<<divup(NN, 256), 256, 0, s_side>>>(cnt, dinv);
    scan1<<<SCAN_NB, SCAN_BS, 0, s_side>>>(cnt, bsum);
    scan2<<<1, 1024, 0, s_side>>>(bsum);
    scan3<<<SCAN_NB, SCAN_BS, 0, s_side>>>(cnt, bsum, off);
    k_copy_i<<<divup(NN, 256), 256, 0, s_side>>>(off, cur, NN);
    k_bucket<<<divup(NE2, 256), 256, 0, s_side>>>(src, dst, dinv, cur, cs, cw);
    cudaEventRecord(s_ev1, s_side);
    cudaStreamWaitEvent(MAIN, s_ev1, 0);

    // ---- x1 = relu(prop(x@W1)+b1) ----
    prop_launch<64, 0>(A, x1, b1, off, cs, cw);

    // ---- x2 = relu(prop(x1@W2)+b2) ----
    gemm(x1, wt + WOFF_W2, A, NN, 256, 128, 0, 0.0f, nullptr, MAIN);
    prop_launch<32, 0>(A, x2, b2, off, cs, cw);

    // ---- x3 = relu(prop(x2@W3)+b3)  (64) ----
    gemm(x2, wt + WOFF_W3, A, NN, 128, 64, 0, 0.0f, nullptr, MAIN);
    prop_launch<16, 0>(A, B, b3, off, cs, cw);

    // ---- x3 = relu(prop(x3@W4)+b4)  (32) ----
    gemm(B, wt + WOFF_W4, A, NN, 64, 32, 0, 0.0f, nullptr, MAIN);
    prop_launch<8, 0>(A, B, b4, off, cs, cw);

    // ---- GATv2 (128); xl=C (main), xr=A (side) — fused flash-softmax ----
    cudaEventRecord(s_ev2, MAIN);
    cudaStreamWaitEvent(s_side, s_ev2, 0);
    gemm(B, wt + WOFF_WR, A, NN, 32, 128, 0, 0.0f, nullptr, s_side);
    cudaEventRecord(s_ev3, s_side);
    gemm(B, wt + WOFF_WL, C, NN, 32, 128, 0, 0.0f, nullptr, MAIN);
    cudaStreamWaitEvent(MAIN, s_ev3, 0);
    gat_fused<<<divup((long long)NN * 32, 256), 256>>>(
        (const float4*)C, (const float4*)A, off, cs,
        (const float4*)att, bg, (float4*)D);

    // ---- GCN2 #1 with x0=x2 (128) ----
    prop_launch<32, 1>(D, A, x2, off, cs, cw);
    gemm(A, wt + WOFF_WC1, B, NN, 128, 128, 1, BETA, nullptr, MAIN);

    // ---- x3 = relu(prop(B)@W5 + b5)  (prop commuted to 128-d) ----
    prop_launch<32, 3>(B, A, nullptr, off, cs, cw);
    gemm(A, wt + WOFF_W5, C, NN, 128, 256, 2, 0.0f, b5, MAIN);

    // ---- GCN2 #2 with x0=x1 (256) ----
    prop_launch<64, 1>(C, A, x1, off, cs, cw);
    gemm(A, wt + WOFF_WC2, B, NN, 256, 256, 1, BETA, nullptr, MAIN);

    // ---- out = prop(x3@Wo) + bo ----
    gemm(B, wt + WOFF_WO, A, NN, 256, 128, 0, 0.0f, nullptr, MAIN);
    prop_launch<32, 2>(A, out, bo, off, cs, cw);
}

// round 14
// speedup vs baseline: 1.0881x; 1.0881x over previous
#include <cuda_runtime.h>
#include <cuda_bf16.h>
#include <cstdint>
#include <math.h>

#define NN 50000
#define NE 800000
#define NE2 850000
#define SCAN_BS 512
#define SCAN_NB ((NN + SCAN_BS - 1) / SCAN_BS)

// ---------------- device scratch ----------------
__device__ __align__(16) float g_x1[(size_t)NN * 256];
__device__ __align__(16) float g_x2[(size_t)NN * 128];
__device__ __align__(16) float g_A [(size_t)NN * 256];
__device__ __align__(16) float g_B [(size_t)NN * 256];
__device__ __align__(16) float g_C [(size_t)NN * 256];
__device__ __align__(16) float g_D [(size_t)NN * 128];
__device__ float    g_dinv[NN];
__device__ int      g_src[NE];
__device__ int      g_dst[NE];
__device__ int      g_cnt[NN];
__device__ int      g_off[NN + 1];
__device__ int      g_cur[NN];
__device__ int      g_bsum[SCAN_NB + 32];
__device__ int      g_csr_s[NE2];
__device__ float    g_csr_w[NE2];
__device__ int      g_eflag[1];
__device__ __align__(16) __nv_bfloat16 g_wt[600000];

static inline int divup(long long a, int b) { return (int)((a + b - 1) / b); }

// ---------------- PTX helpers (plain-sm_100 legal) ----------------
__device__ __forceinline__ uint32_t smem_u32(const void* p) {
    uint32_t a;
    asm("{ .reg .u64 t; cvta.to.shared.u64 t, %1; cvt.u32.u64 %0, t; }" : "=r"(a) : "l"(p));
    return a;
}
__device__ __forceinline__ void ldm_x4(uint32_t (&r)[4], uint32_t addr) {
    asm volatile("ldmatrix.sync.aligned.m8n8.x4.shared.b16 {%0,%1,%2,%3}, [%4];"
                 : "=r"(r[0]), "=r"(r[1]), "=r"(r[2]), "=r"(r[3]) : "r"(addr));
}
__device__ __forceinline__ void mma16816(float (&d)[4], const uint32_t (&a)[4],
                                         uint32_t b0, uint32_t b1) {
    asm volatile(
        "mma.sync.aligned.m16n8k16.row.col.f32.bf16.bf16.f32 "
        "{%0,%1,%2,%3}, {%4,%5,%6,%7}, {%8,%9}, {%0,%1,%2,%3};"
        : "+f"(d[0]), "+f"(d[1]), "+f"(d[2]), "+f"(d[3])
        : "r"(a[0]), "r"(a[1]), "r"(a[2]), "r"(a[3]), "r"(b0), "r"(b1));
}

// ---------------- edge-index dtype detection + conversion ----------------
__global__ void k_detect(const int* __restrict__ ei32) {
    __shared__ int cnt;
    if (threadIdx.x == 0) cnt = 0;
    __syncthreads();
    int nz = 0;
    for (int i = threadIdx.x; i < 2048; i += blockDim.x)
        if (ei32[2 * i + 1] != 0) nz++;
    atomicAdd(&cnt, nz);
    __syncthreads();
    if (threadIdx.x == 0) g_eflag[0] = (cnt == 0) ? 1 : 0;
}
__global__ void k_convert(const int* __restrict__ ei32,
                          int* __restrict__ src, int* __restrict__ dst) {
    int e = blockIdx.x * blockDim.x + threadIdx.x;
    if (e >= NE) return;
    int is64 = g_eflag[0];
    int s, d;
    if (is64) { s = ei32[2 * e]; d = ei32[2 * (NE + e)]; }
    else      { s = ei32[e];     d = ei32[NE + e]; }
    s = min(max(s, 0), NN - 1);
    d = min(max(d, 0), NN - 1);
    src[e] = s; dst[e] = d;
}

// ---------------- weight pre-transpose + bf16 split ----------------
__global__ void k_splitw(const float* __restrict__ W, __nv_bfloat16* __restrict__ wt,
                         int m, int k, int mpad) {
    int idx = blockIdx.x * blockDim.x + threadIdx.x;
    int tot = k * mpad;
    if (idx >= tot) return;
    int j = idx / mpad, kk = idx % mpad;
    float f = (kk < m) ? W[(size_t)kk * k + j] : 0.0f;
    __nv_bfloat16 h = __float2bfloat16(f);
    __nv_bfloat16 l = __float2bfloat16(f - __bfloat162float(h));
    wt[idx] = h;
    wt[tot + idx] = l;
}

// ---------------- CSR build ----------------
__global__ void k_fill_i(int* p, int n, int v) {
    int i = blockIdx.x * blockDim.x + threadIdx.x;
    if (i < n) p[i] = v;
}
__global__ void k_count(const int* __restrict__ dst, int* __restrict__ cnt) {
    int e = blockIdx.x * blockDim.x + threadIdx.x;
    if (e < NE) atomicAdd(&cnt[dst[e]], 1);
}
__global__ void k_dinv(const int* __restrict__ cnt, float* __restrict__ dinv) {
    int i = blockIdx.x * blockDim.x + threadIdx.x;
    if (i < NN) dinv[i] = rsqrtf((float)cnt[i]);
}
__global__ void scan1(const int* __restrict__ cnt, int* __restrict__ bsum) {
    __shared__ int sh[SCAN_BS];
    int i = blockIdx.x * SCAN_BS + threadIdx.x;
    sh[threadIdx.x] = (i < NN) ? cnt[i] : 0;
    __syncthreads();
    for (int s = SCAN_BS / 2; s; s >>= 1) {
        if (threadIdx.x < s) sh[threadIdx.x] += sh[threadIdx.x + s];
        __syncthreads();
    }
    if (threadIdx.x == 0) bsum[blockIdx.x] = sh[0];
}
__global__ void scan2(int* __restrict__ bsum) {
    __shared__ int sh[1024];
    int v = (threadIdx.x < SCAN_NB) ? bsum[threadIdx.x] : 0;
    sh[threadIdx.x] = v;
    __syncthreads();
    for (int o = 1; o < 1024; o <<= 1) {
        int t = (threadIdx.x >= o) ? sh[threadIdx.x - o] : 0;
        __syncthreads();
        sh[threadIdx.x] += t;
        __syncthreads();
    }
    if (threadIdx.x < SCAN_NB) bsum[threadIdx.x] = sh[threadIdx.x] - v;
}
__global__ void scan3(const int* __restrict__ cnt, const int* __restrict__ bsum,
                      int* __restrict__ off) {
    __shared__ int sh[SCAN_BS];
    int i = blockIdx.x * SCAN_BS + threadIdx.x;
    int v = (i < NN) ? cnt[i] : 0;
    sh[threadIdx.x] = v;
    __syncthreads();
    for (int o = 1; o < SCAN_BS; o <<= 1) {
        int t = (threadIdx.x >= o) ? sh[threadIdx.x - o] : 0;
        __syncthreads();
        sh[threadIdx.x] += t;
        __syncthreads();
    }
    if (i <= NN) off[i] = bsum[blockIdx.x] + sh[threadIdx.x] - v;
}
__global__ void k_copy_i(const int* __restrict__ a, int* __restrict__ b, int n) {
    int i = blockIdx.x * blockDim.x + threadIdx.x;
    if (i < n) b[i] = a[i];
}
__global__ void k_bucket(const int* __restrict__ src, const int* __restrict__ dst,
                         const float* __restrict__ dinv, int* __restrict__ cur,
                         int* __restrict__ cs, float* __restrict__ cw) {
    int t = blockIdx.x * blockDim.x + threadIdx.x;
    if (t >= NE2) return;
    int s, d;
    if (t < NE) { s = src[t]; d = dst[t]; }
    else        { s = d = t - NE; }
    int pos = atomicAdd(&cur[d], 1);
    cs[pos] = s;
    cw[pos] = dinv[s] * dinv[d];
}

// ---------------- mma.sync bf16x3 GEMM (R11 single-buffer, regs<=128) ----------------
// Block 128x128, 8 warps (4 M x 2 N), warp tile 32x64, K-tile 32 (2 x k16).
// EPI: 0 none, 1 GCN2 relu((1-b)A + b*AW) (m==k), 2 relu(AW + bias)
#define LDS_B 80
template <int EPI>
__global__ __launch_bounds__(256) void gemm_mma(
    const float* __restrict__ A, const __nv_bfloat16* __restrict__ Wt,
    float* __restrict__ C, int n, int m, int k, int mpad, float beta,
    const float* __restrict__ bias) {
    __shared__ __align__(16) char sAh[128 * LDS_B];
    __shared__ __align__(16) char sAl[128 * LDS_B];
    __shared__ __align__(16) char sBh[128 * LDS_B];
    __shared__ __align__(16) char sBl[128 * LDS_B];

    const int tid  = threadIdx.x;
    const int wid  = tid >> 5, lane = tid & 31;
    const int warp_m = wid & 3, warp_n = wid >> 2;
    const int row0 = blockIdx.y * 128;
    const int col0 = blockIdx.x * 128;
    const int planeoff = k * mpad;

    const uint32_t ah_b = smem_u32(sAh), al_b = smem_u32(sAl);
    const uint32_t bh_b = smem_u32(sBh), bl_b = smem_u32(sBl);
    const int lr = lane & 15, lc = lane >> 4;
    const uint32_t a_off = (uint32_t)(warp_m * 32 + lr) * LDS_B + lc * 16;
    const uint32_t b_off = (uint32_t)(warp_n * 64 + lr) * LDS_B + lc * 16;

    float acc[2][8][4];
    #pragma unroll
    for (int i = 0; i < 2; i++)
        #pragma unroll
        for (int j = 0; j < 8; j++)
            #pragma unroll
            for (int r = 0; r < 4; r++) acc[i][j][r] = 0.0f;

    const uint4 Z4 = make_uint4(0, 0, 0, 0);

    for (int kt = 0; kt < mpad; kt += 32) {
        __syncthreads();
        // ---- A tile: 128 x 32 fp32 -> bf16 hi/lo ----
        #pragma unroll
        for (int i = 0; i < 4; i++) {
            int idx = tid + i * 256;
            int r = idx >> 3, q = idx & 7;
            int gr = row0 + r, gk = kt + q * 4;
            float4 v = make_float4(0.f, 0.f, 0.f, 0.f);
            if (gr < n && gk < m) v = *(const float4*)&A[(size_t)gr * m + gk];
            __nv_bfloat16 h0 = __float2bfloat16(v.x), h1 = __float2bfloat16(v.y);
            __nv_bfloat16 h2 = __float2bfloat16(v.z), h3 = __float2bfloat16(v.w);
            __nv_bfloat16 l0 = __float2bfloat16(v.x - __bfloat162float(h0));
            __nv_bfloat16 l1 = __float2bfloat16(v.y - __bfloat162float(h1));
            __nv_bfloat16 l2 = __float2bfloat16(v.z - __bfloat162float(h2));
            __nv_bfloat16 l3 = __float2bfloat16(v.w - __bfloat162float(h3));
            __nv_bfloat162 hp0 = {h0, h1}, hp1 = {h2, h3};
            __nv_bfloat162 lp0 = {l0, l1}, lp1 = {l2, l3};
            uint2 uh = make_uint2(*(uint32_t*)&hp0, *(uint32_t*)&hp1);
            uint2 ul = make_uint2(*(uint32_t*)&lp0, *(uint32_t*)&lp1);
            *(uint2*)(sAh + r * LDS_B + q * 8) = uh;
            *(uint2*)(sAl + r * LDS_B + q * 8) = ul;
        }
        // ---- B tile: 128 n-rows x 32 k bf16 (pre-split) ----
        #pragma unroll
        for (int i = 0; i < 2; i++) {
            int idx = tid + i * 256;
            int j = idx >> 2, kq = idx & 3;
            int gj = col0 + j;
            uint4 vh = Z4, vl = Z4;
            if (gj < k) {
                size_t g = (size_t)gj * mpad + kt + kq * 8;
                vh = *(const uint4*)&Wt[g];
                vl = *(const uint4*)&Wt[planeoff + g];
            }
            *(uint4*)(sBh + j * LDS_B + kq * 16) = vh;
            *(uint4*)(sBl + j * LDS_B + kq * 16) = vl;
        }
        __syncthreads();

        #pragma unroll
        for (int ks = 0; ks < 2; ks++) {
            const uint32_t kb2 = ks * 32;
            uint32_t ah[2][4], al[2][4], bh[4][4], bl[4][4];
            #pragma unroll
            for (int mt = 0; mt < 2; mt++) {
                ldm_x4(ah[mt], ah_b + a_off + mt * (16 * LDS_B) + kb2);
                ldm_x4(al[mt], al_b + a_off + mt * (16 * LDS_B) + kb2);
            }
            #pragma unroll
            for (int nt = 0; nt < 4; nt++) {
                ldm_x4(bh[nt], bh_b + b_off + nt * (16 * LDS_B) + kb2);
                ldm_x4(bl[nt], bl_b + b_off + nt * (16 * LDS_B) + kb2);
            }
            #pragma unroll
            for (int mt = 0; mt < 2; mt++)
                #pragma unroll
                for (int nt = 0; nt < 4; nt++) {
                    mma16816(acc[mt][nt*2+0], ah[mt], bh[nt][0], bh[nt][2]);
                    mma16816(acc[mt][nt*2+1], ah[mt], bh[nt][1], bh[nt][3]);
                    mma16816(acc[mt][nt*2+0], ah[mt], bl[nt][0], bl[nt][2]);
                    mma16816(acc[mt][nt*2+1], ah[mt], bl[nt][1], bl[nt][3]);
                    mma16816(acc[mt][nt*2+0], al[mt], bh[nt][0], bh[nt][2]);
                    mma16816(acc[mt][nt*2+1], al[mt], bh[nt][1], bh[nt][3]);
                }
        }
    }

    // ---- epilogue ----
    const int g = lane >> 2, t = lane & 3;
    #pragma unroll
    for (int mt = 0; mt < 2; mt++) {
        #pragma unroll
        for (int ntg = 0; ntg < 8; ntg++) {
            int gc = col0 + warp_n * 64 + ntg * 8 + t * 2;
            if (gc >= k) continue;
            #pragma unroll
            for (int half = 0; half < 2; half++) {
                int gr = row0 + warp_m * 32 + mt * 16 + g + half * 8;
                if (gr >= n) continue;
                float c0 = acc[mt][ntg][half * 2 + 0];
                float c1 = acc[mt][ntg][half * 2 + 1];
                if (EPI == 1) {
                    float2 x0 = *(const float2*)&A[(size_t)gr * m + gc];
                    c0 = fmaxf(beta * c0 + (1.0f - beta) * x0.x, 0.f);
                    c1 = fmaxf(beta * c1 + (1.0f - beta) * x0.y, 0.f);
                } else if (EPI == 2) {
                    float2 b = *(const float2*)&bias[gc];
                    c0 = fmaxf(c0 + b.x, 0.f);
                    c1 = fmaxf(c1 + b.y, 0.f);
                }
                *(float2*)&C[(size_t)gr * k + gc] = make_float2(c0, c1);
            }
        }
    }
}

// ---------------- pull-based GCN propagation (unroll 4) ----------------
template <int D4, int MODE>
__global__ void prop_pull(const float4* __restrict__ h, float4* __restrict__ o,
                          const float* __restrict__ aux,
                          const int* __restrict__ off, const int* __restrict__ csr_s,
                          const float* __restrict__ csr_w) {
    constexpr int TPN = (D4 < 32) ? D4 : 32;
    constexpr int NPW = 32 / TPN;
    constexpr int R   = D4 / TPN;
    int gwarp = (blockIdx.x * blockDim.x + threadIdx.x) >> 5;
    int lane  = threadIdx.x & 31;
    int node  = gwarp * NPW + lane / TPN;
    int tl    = lane % TPN;
    if (node >= NN) return;

    float4 acc[R];
    #pragma unroll
    for (int r = 0; r < R; r++) acc[r] = make_float4(0.f, 0.f, 0.f, 0.f);

    int j0 = off[node], j1 = off[node + 1];
    int j = j0;
    for (; j + 3 < j1; j += 4) {
        int   s0 = csr_s[j],   s1 = csr_s[j+1], s2 = csr_s[j+2], s3 = csr_s[j+3];
        float w0 = csr_w[j],   w1 = csr_w[j+1], w2 = csr_w[j+2], w3 = csr_w[j+3];
        #pragma unroll
        for (int r = 0; r < R; r++) {
            float4 v0 = h[(size_t)s0 * D4 + tl + r * TPN];
            float4 v1 = h[(size_t)s1 * D4 + tl + r * TPN];
            float4 v2 = h[(size_t)s2 * D4 + tl + r * TPN];
            float4 v3 = h[(size_t)s3 * D4 + tl + r * TPN];
            acc[r].x += w0*v0.x + w1*v1.x + w2*v2.x + w3*v3.x;
            acc[r].y += w0*v0.y + w1*v1.y + w2*v2.y + w3*v3.y;
            acc[r].z += w0*v0.z + w1*v1.z + w2*v2.z + w3*v3.z;
            acc[r].w += w0*v0.w + w1*v1.w + w2*v2.w + w3*v3.w;
        }
    }
    for (; j < j1; j++) {
        int s0 = csr_s[j];
        float w0 = csr_w[j];
        #pragma unroll
        for (int r = 0; r < R; r++) {
            float4 v0 = h[(size_t)s0 * D4 + tl + r * TPN];
            acc[r].x += w0 * v0.x; acc[r].y += w0 * v0.y;
            acc[r].z += w0 * v0.z; acc[r].w += w0 * v0.w;
        }
    }

    const float4* aux4 = (const float4*)aux;
    #pragma unroll
    for (int r = 0; r < R; r++) {
        int c = tl + r * TPN;
        float4 v = acc[r];
        if (MODE == 0 || MODE == 2) {
            float4 b = aux4[c];
            v.x += b.x; v.y += b.y; v.z += b.z; v.w += b.w;
            if (MODE == 0) {
                v.x = fmaxf(v.x, 0.f); v.y = fmaxf(v.y, 0.f);
                v.z = fmaxf(v.z, 0.f); v.w = fmaxf(v.w, 0.f);
            }
        } else if (MODE == 1) {
            float4 x0 = aux4[(size_t)node * D4 + c];
            v.x = 0.5f * (v.x + x0.x); v.y = 0.5f * (v.y + x0.y);
            v.z = 0.5f * (v.z + x0.z); v.w = 0.5f * (v.w + x0.w);
        }
        o[(size_t)node * D4 + c] = v;
    }
}

// ---------------- GATv2: fused flash-softmax, 2-edge unrolled ----------------
__global__ void gat_fused(const float4* __restrict__ xl4, const float4* __restrict__ xr4,
                          const int* __restrict__ off, const int* __restrict__ cs,
                          const float4* __restrict__ att4, const float* __restrict__ bg,
                          float4* __restrict__ out) {
    int node = (blockIdx.x * blockDim.x + threadIdx.x) >> 5;
    int lane = threadIdx.x & 31;
    if (node >= NN) return;
    int j0 = off[node], j1 = off[node + 1];

    float4 xr = xr4[(size_t)node * 32 + lane];
    float4 at = att4[lane];

    float m = -1e30f, s = 0.0f;
    float4 acc = make_float4(0.f, 0.f, 0.f, 0.f);

    int j = j0;
    for (; j + 1 < j1; j += 2) {
        int sa = cs[j], sb = cs[j + 1];
        float4 va = xl4[(size_t)sa * 32 + lane];
        float4 vb = xl4[(size_t)sb * 32 + lane];
        float a0 = va.x + xr.x; a0 = (a0 > 0.f) ? a0 : 0.2f * a0;
        float a1 = va.y + xr.y; a1 = (a1 > 0.f) ? a1 : 0.2f * a1;
        float a2 = va.z + xr.z; a2 = (a2 > 0.f) ? a2 : 0.2f * a2;
        float a3 = va.w + xr.w; a3 = (a3 > 0.f) ? a3 : 0.2f * a3;
        float b0 = vb.x + xr.x; b0 = (b0 > 0.f) ? b0 : 0.2f * b0;
        float b1 = vb.y + xr.y; b1 = (b1 > 0.f) ? b1 : 0.2f * b1;
        float b2 = vb.z + xr.z; b2 = (b2 > 0.f) ? b2 : 0.2f * b2;
        float b3 = vb.w + xr.w; b3 = (b3 > 0.f) ? b3 : 0.2f * b3;
        float pa = a0 * at.x + a1 * at.y + a2 * at.z + a3 * at.w;
        float pb = b0 * at.x + b1 * at.y + b2 * at.z + b3 * at.w;
        pa += __shfl_xor_sync(0xffffffffu, pa, 1);
        pb += __shfl_xor_sync(0xffffffffu, pb, 1);
        pa += __shfl_xor_sync(0xffffffffu, pa, 2);
        pb += __shfl_xor_sync(0xffffffffu, pb, 2);
        pa += __shfl_xor_sync(0xffffffffu, pa, 4);
        pb += __shfl_xor_sync(0xffffffffu, pb, 4);
        float nm = fmaxf(m, fmaxf(pa, pb));
        float r  = __expf(m - nm);
        float wa = __expf(pa - nm);
        float wb = __expf(pb - nm);
        s = s * r + wa + wb;
        acc.x = acc.x * r + wa * va.x + wb * vb.x;
        acc.y = acc.y * r + wa * va.y + wb * vb.y;
        acc.z = acc.z * r + wa * va.z + wb * vb.z;
        acc.w = acc.w * r + wa * va.w + wb * vb.w;
        m = nm;
    }
    if (j < j1) {
        int sn = cs[j];
        float4 v = xl4[(size_t)sn * 32 + lane];
        float e0 = v.x + xr.x; e0 = (e0 > 0.f) ? e0 : 0.2f * e0;
        float e1 = v.y + xr.y; e1 = (e1 > 0.f) ? e1 : 0.2f * e1;
        float e2 = v.z + xr.z; e2 = (e2 > 0.f) ? e2 : 0.2f * e2;
        float e3 = v.w + xr.w; e3 = (e3 > 0.f) ? e3 : 0.2f * e3;
        float p = e0 * at.x + e1 * at.y + e2 * at.z + e3 * at.w;
        p += __shfl_xor_sync(0xffffffffu, p, 1);
        p += __shfl_xor_sync(0xffffffffu, p, 2);
        p += __shfl_xor_sync(0xffffffffu, p, 4);
        float nm = fmaxf(m, p);
        float r  = __expf(m - nm);
        float w  = __expf(p - nm);
        s = s * r + w;
        acc.x = acc.x * r + w * v.x;
        acc.y = acc.y * r + w * v.y;
        acc.z = acc.z * r + w * v.z;
        acc.w = acc.w * r + w * v.w;
        m = nm;
    }
    float inv = 1.0f / (s + 1e-16f);
    float4 b = ((const float4*)bg)[lane];
    acc.x = fmaxf(acc.x * inv + b.x, 0.f);
    acc.y = fmaxf(acc.y * inv + b.y, 0.f);
    acc.z = fmaxf(acc.z * inv + b.z, 0.f);
    acc.w = fmaxf(acc.w * inv + b.w, 0.f);
    out[(size_t)node * 32 + lane] = acc;
}

// ---------------- host helpers ----------------
static inline int mpad32(int m) { return ((m + 31) / 32) * 32; }

static void gemm(const float* A, const __nv_bfloat16* Wt, float* C,
                 int n, int m, int k, int epi, float beta, const float* bias,
                 cudaStream_t st) {
    int mp = mpad32(m);
    dim3 grid(divup(k, 128), divup(n, 128));
    if (epi == 1)      gemm_mma<1><<<grid, 256, 0, st>>>(A, Wt, C, n, m, k, mp, beta, nullptr);
    else if (epi == 2) gemm_mma<2><<<grid, 256, 0, st>>>(A, Wt, C, n, m, k, mp, 0.0f, bias);
    else               gemm_mma<0><<<grid, 256, 0, st>>>(A, Wt, C, n, m, k, mp, 0.0f, nullptr);
}

template <int D4, int MODE>
static void prop_launch(const float* h, float* o, const float* aux,
                        const int* off, const int* cs, const float* cw) {
    constexpr int NPW = (D4 < 32) ? (32 / D4) : 1;
    int warps = divup(NN, NPW);
    prop_pull<D4, MODE><<<divup((long long)warps * 32, 256), 256>>>(
        (const float4*)h, (float4*)o, aux, off, cs, cw);
}

static cudaStream_t s_side = nullptr;
static cudaEvent_t  s_ev0, s_ev1, s_ev2, s_ev3;

#define WOFF_W1  0
#define WOFF_W2  (WOFF_W1  + 2 * 256 * 320)
#define WOFF_W3  (WOFF_W2  + 2 * 128 * 256)
#define WOFF_W4  (WOFF_W3  + 2 * 64 * 128)
#define WOFF_WL  (WOFF_W4  + 2 * 32 * 64)
#define WOFF_WR  (WOFF_WL  + 2 * 128 * 32)
#define WOFF_WC1 (WOFF_WR  + 2 * 128 * 32)
#define WOFF_W5  (WOFF_WC1 + 2 * 128 * 128)
#define WOFF_WC2 (WOFF_W5  + 2 * 256 * 128)
#define WOFF_WO  (WOFF_WC2 + 2 * 256 * 256)

extern "C" void kernel_launch(void* const* d_in, const int* in_sizes, int n_in,
                              void* d_out, int out_size) {
    if (!s_side) {
        cudaStreamCreateWithFlags(&s_side, cudaStreamNonBlocking);
        cudaEventCreateWithFlags(&s_ev0, cudaEventDisableTiming);
        cudaEventCreateWithFlags(&s_ev1, cudaEventDisableTiming);
        cudaEventCreateWithFlags(&s_ev2, cudaEventDisableTiming);
        cudaEventCreateWithFlags(&s_ev3, cudaEventDisableTiming);
    }
    const cudaStream_t MAIN = 0;

    const float* x   = (const float*)d_in[0];
    const int*   ei32= (const int*)d_in[1];
    const float* W1 = (const float*)d_in[2];  const float* b1 = (const float*)d_in[3];
    const float* W2 = (const float*)d_in[4];  const float* b2 = (const float*)d_in[5];
    const float* W3 = (const float*)d_in[6];  const float* b3 = (const float*)d_in[7];
    const float* W4 = (const float*)d_in[8];  const float* b4 = (const float*)d_in[9];
    const float* Wl = (const float*)d_in[10]; const float* Wr = (const float*)d_in[11];
    const float* att= (const float*)d_in[12]; const float* bg = (const float*)d_in[13];
    const float* Wc1= (const float*)d_in[14];
    const float* W5 = (const float*)d_in[15]; const float* b5 = (const float*)d_in[16];
    const float* Wc2= (const float*)d_in[17];
    const float* Wo = (const float*)d_in[18]; const float* bo = (const float*)d_in[19];
    float* out = (float*)d_out;

    float *x1, *x2, *A, *B, *C, *D, *dinv, *cw;
    int *src, *dst, *cnt, *off, *cur, *bsum, *cs;
    __nv_bfloat16* wt;
    cudaGetSymbolAddress((void**)&x1,   g_x1);
    cudaGetSymbolAddress((void**)&x2,   g_x2);
    cudaGetSymbolAddress((void**)&A,    g_A);
    cudaGetSymbolAddress((void**)&B,    g_B);
    cudaGetSymbolAddress((void**)&C,    g_C);
    cudaGetSymbolAddress((void**)&D,    g_D);
    cudaGetSymbolAddress((void**)&dinv, g_dinv);
    cudaGetSymbolAddress((void**)&src,  g_src);
    cudaGetSymbolAddress((void**)&dst,  g_dst);
    cudaGetSymbolAddress((void**)&cnt,  g_cnt);
    cudaGetSymbolAddress((void**)&off,  g_off);
    cudaGetSymbolAddress((void**)&cur,  g_cur);
    cudaGetSymbolAddress((void**)&bsum, g_bsum);
    cudaGetSymbolAddress((void**)&cs,   g_csr_s);
    cudaGetSymbolAddress((void**)&cw,   g_csr_w);
    cudaGetSymbolAddress((void**)&wt,   g_wt);

    const float BETA = logf(1.05f);

    // ---- head: detect(1), convert(2), splitW1(3), gemm1(4 <- profiled) ----
    k_detect<<<1, 256>>>(ei32);
    k_convert<<<divup(NE, 256), 256>>>(ei32, src, dst);
    k_splitw<<<divup(256 * 320, 256), 256>>>(W1, wt + WOFF_W1, 300, 256, 320);
    gemm(x, wt + WOFF_W1, A, NN, 300, 256, 0, 0.0f, nullptr, MAIN);
    cudaEventRecord(s_ev0, MAIN);
    cudaStreamWaitEvent(s_side, s_ev0, 0);

    // side stream: remaining weight splits + CSR build
    k_splitw<<<divup(128 * 256, 256), 256, 0, s_side>>>(W2,  wt + WOFF_W2,  256, 128, 256);
    k_splitw<<<divup(64 * 128, 256),  256, 0, s_side>>>(W3,  wt + WOFF_W3,  128, 64, 128);
    k_splitw<<<divup(32 * 64, 256),   256, 0, s_side>>>(W4,  wt + WOFF_W4,  64, 32, 64);
    k_splitw<<<divup(128 * 32, 256),  256, 0, s_side>>>(Wl,  wt + WOFF_WL,  32, 128, 32);
    k_splitw<<<divup(128 * 32, 256),  256, 0, s_side>>>(Wr,  wt + WOFF_WR,  32, 128, 32);
    k_splitw<<<divup(128 * 128, 256), 256, 0, s_side>>>(Wc1, wt + WOFF_WC1, 128, 128, 128);
    k_splitw<<<divup(256 * 128, 256), 256, 0, s_side>>>(W5,  wt + WOFF_W5,  128, 256, 128);
    k_splitw<<<divup(256 * 256, 256), 256, 0, s_side>>>(Wc2, wt + WOFF_WC2, 256, 256, 256);
    k_splitw<<<divup(128 * 256, 256), 256, 0, s_side>>>(Wo,  wt + WOFF_WO,  256, 128, 256);
    k_fill_i<<<divup(NN, 256), 256, 0, s_side>>>(cnt, NN, 1);
    k_count<<<divup(NE, 256), 256, 0, s_side>>>(dst, cnt);
    k_dinv<<<divup(NN, 256), 256, 0, s_side>>>(cnt, dinv);
    scan1<<<SCAN_NB, SCAN_BS, 0, s_side>>>(cnt, bsum);
    scan2<<<1, 1024, 0, s_side>>>(bsum);
    scan3<<<SCAN_NB, SCAN_BS, 0, s_side>>>(cnt, bsum, off);
    k_copy_i<<<divup(NN, 256), 256, 0, s_side>>>(off, cur, NN);
    k_bucket<<<divup(NE2, 256), 256, 0, s_side>>>(src, dst, dinv, cur, cs, cw);
    cudaEventRecord(s_ev1, s_side);
    cudaStreamWaitEvent(MAIN, s_ev1, 0);

    // ---- x1 = relu(prop(x@W1)+b1) ----
    prop_launch<64, 0>(A, x1, b1, off, cs, cw);

    // ---- x2 = relu(prop(x1@W2)+b2) ----
    gemm(x1, wt + WOFF_W2, A, NN, 256, 128, 0, 0.0f, nullptr, MAIN);
    prop_launch<32, 0>(A, x2, b2, off, cs, cw);

    // ---- x3 = relu(prop(x2@W3)+b3)  (64) ----
    gemm(x2, wt + WOFF_W3, A, NN, 128, 64, 0, 0.0f, nullptr, MAIN);
    prop_launch<16, 0>(A, B, b3, off, cs, cw);

    // ---- x3 = relu(prop(x3@W4)+b4)  (32) ----
    gemm(B, wt + WOFF_W4, A, NN, 64, 32, 0, 0.0f, nullptr, MAIN);
    prop_launch<8, 0>(A, B, b4, off, cs, cw);

    // ---- GATv2 (128); xl=C (main), xr=A (side) — fused flash-softmax ----
    cudaEventRecord(s_ev2, MAIN);
    cudaStreamWaitEvent(s_side, s_ev2, 0);
    gemm(B, wt + WOFF_WR, A, NN, 32, 128, 0, 0.0f, nullptr, s_side);
    cudaEventRecord(s_ev3, s_side);
    gemm(B, wt + WOFF_WL, C, NN, 32, 128, 0, 0.0f, nullptr, MAIN);
    cudaStreamWaitEvent(MAIN, s_ev3, 0);
    gat_fused<<<divup((long long)NN * 32, 256), 256>>>(
        (const float4*)C, (const float4*)A, off, cs,
        (const float4*)att, bg, (float4*)D);

    // ---- GCN2 #1 with x0=x2 (128) ----
    prop_launch<32, 1>(D, A, x2, off, cs, cw);
    gemm(A, wt + WOFF_WC1, B, NN, 128, 128, 1, BETA, nullptr, MAIN);

    // ---- x3 = relu(prop(B)@W5 + b5)  (prop commuted to 128-d) ----
    prop_launch<32, 3>(B, A, nullptr, off, cs, cw);
    gemm(A, wt + WOFF_W5, C, NN, 128, 256, 2, 0.0f, b5, MAIN);

    // ---- GCN2 #2 with x0=x1 (256) ----
    prop_launch<64, 1>(C, A, x1, off, cs, cw);
    gemm(A, wt + WOFF_WC2, B, NN, 256, 256, 1, BETA, nullptr, MAIN);

    // ---- out = prop(x3@Wo) + bo ----
    gemm(B, wt + WOFF_WO, A, NN, 256, 128, 0, 0.0f, nullptr, MAIN);
    prop_launch<32, 2>(A, out, bo, off, cs, cw);
}

// round 15
// speedup vs baseline: 1.1151x; 1.0248x over previous
#include <cuda_runtime.h>
#include <cuda_bf16.h>
#include <cstdint>
#include <math.h>

#define NN 50000
#define NE 800000
#define NE2 850000
#define SCAN_BS 512
#define SCAN_NB ((NN + SCAN_BS - 1) / SCAN_BS)

// ---------------- device scratch ----------------
__device__ __align__(16) float g_x1[(size_t)NN * 256];
__device__ __align__(16) float g_x2[(size_t)NN * 128];
__device__ __align__(16) float g_A [(size_t)NN * 256];
__device__ __align__(16) float g_B [(size_t)NN * 256];
__device__ __align__(16) float g_C [(size_t)NN * 256];
__device__ __align__(16) float g_D [(size_t)NN * 128];
__device__ float    g_dinv[NN];
__device__ int      g_src[NE];
__device__ int      g_dst[NE];
__device__ int      g_cnt[NN];
__device__ int      g_off[NN + 1];
__device__ int      g_cur[NN];
__device__ int      g_bsum[SCAN_NB + 32];
__device__ int      g_csr_s[NE2];
__device__ float    g_csr_w[NE2];
__device__ int      g_eflag[1];
__device__ __align__(16) __nv_bfloat16 g_wt[600000];

static inline int divup(long long a, int b) { return (int)((a + b - 1) / b); }

// ---------------- PTX helpers (plain-sm_100 legal) ----------------
__device__ __forceinline__ uint32_t smem_u32(const void* p) {
    uint32_t a;
    asm("{ .reg .u64 t; cvta.to.shared.u64 t, %1; cvt.u32.u64 %0, t; }" : "=r"(a) : "l"(p));
    return a;
}
__device__ __forceinline__ void ldm_x4(uint32_t (&r)[4], uint32_t addr) {
    asm volatile("ldmatrix.sync.aligned.m8n8.x4.shared.b16 {%0,%1,%2,%3}, [%4];"
                 : "=r"(r[0]), "=r"(r[1]), "=r"(r[2]), "=r"(r[3]) : "r"(addr));
}
__device__ __forceinline__ void mma16816(float (&d)[4], const uint32_t (&a)[4],
                                         uint32_t b0, uint32_t b1) {
    asm volatile(
        "mma.sync.aligned.m16n8k16.row.col.f32.bf16.bf16.f32 "
        "{%0,%1,%2,%3}, {%4,%5,%6,%7}, {%8,%9}, {%0,%1,%2,%3};"
        : "+f"(d[0]), "+f"(d[1]), "+f"(d[2]), "+f"(d[3])
        : "r"(a[0]), "r"(a[1]), "r"(a[2]), "r"(a[3]), "r"(b0), "r"(b1));
}

// ---------------- edge-index dtype detection + conversion ----------------
__global__ void k_detect(const int* __restrict__ ei32) {
    __shared__ int cnt;
    if (threadIdx.x == 0) cnt = 0;
    __syncthreads();
    int nz = 0;
    for (int i = threadIdx.x; i < 2048; i += blockDim.x)
        if (ei32[2 * i + 1] != 0) nz++;
    atomicAdd(&cnt, nz);
    __syncthreads();
    if (threadIdx.x == 0) g_eflag[0] = (cnt == 0) ? 1 : 0;
}
__global__ void k_convert(const int* __restrict__ ei32,
                          int* __restrict__ src, int* __restrict__ dst) {
    int e = blockIdx.x * blockDim.x + threadIdx.x;
    if (e >= NE) return;
    int is64 = g_eflag[0];
    int s, d;
    if (is64) { s = ei32[2 * e]; d = ei32[2 * (NE + e)]; }
    else      { s = ei32[e];     d = ei32[NE + e]; }
    s = min(max(s, 0), NN - 1);
    d = min(max(d, 0), NN - 1);
    src[e] = s; dst[e] = d;
}

// ---------------- weight pre-transpose + bf16 split ----------------
__global__ void k_splitw(const float* __restrict__ W, __nv_bfloat16* __restrict__ wt,
                         int m, int k, int mpad) {
    int idx = blockIdx.x * blockDim.x + threadIdx.x;
    int tot = k * mpad;
    if (idx >= tot) return;
    int j = idx / mpad, kk = idx % mpad;
    float f = (kk < m) ? W[(size_t)kk * k + j] : 0.0f;
    __nv_bfloat16 h = __float2bfloat16(f);
    __nv_bfloat16 l = __float2bfloat16(f - __bfloat162float(h));
    wt[idx] = h;
    wt[tot + idx] = l;
}

// ---------------- CSR build ----------------
__global__ void k_fill_i(int* p, int n, int v) {
    int i = blockIdx.x * blockDim.x + threadIdx.x;
    if (i < n) p[i] = v;
}
__global__ void k_count(const int* __restrict__ dst, int* __restrict__ cnt) {
    int e = blockIdx.x * blockDim.x + threadIdx.x;
    if (e < NE) atomicAdd(&cnt[dst[e]], 1);
}
__global__ void k_dinv(const int* __restrict__ cnt, float* __restrict__ dinv) {
    int i = blockIdx.x * blockDim.x + threadIdx.x;
    if (i < NN) dinv[i] = rsqrtf((float)cnt[i]);
}
__global__ void scan1(const int* __restrict__ cnt, int* __restrict__ bsum) {
    __shared__ int sh[SCAN_BS];
    int i = blockIdx.x * SCAN_BS + threadIdx.x;
    sh[threadIdx.x] = (i < NN) ? cnt[i] : 0;
    __syncthreads();
    for (int s = SCAN_BS / 2; s; s >>= 1) {
        if (threadIdx.x < s) sh[threadIdx.x] += sh[threadIdx.x + s];
        __syncthreads();
    }
    if (threadIdx.x == 0) bsum[blockIdx.x] = sh[0];
}
__global__ void scan2(int* __restrict__ bsum) {
    __shared__ int sh[1024];
    int v = (threadIdx.x < SCAN_NB) ? bsum[threadIdx.x] : 0;
    sh[threadIdx.x] = v;
    __syncthreads();
    for (int o = 1; o < 1024; o <<= 1) {
        int t = (threadIdx.x >= o) ? sh[threadIdx.x - o] : 0;
        __syncthreads();
        sh[threadIdx.x] += t;
        __syncthreads();
    }
    if (threadIdx.x < SCAN_NB) bsum[threadIdx.x] = sh[threadIdx.x] - v;
}
__global__ void scan3(const int* __restrict__ cnt, const int* __restrict__ bsum,
                      int* __restrict__ off) {
    __shared__ int sh[SCAN_BS];
    int i = blockIdx.x * SCAN_BS + threadIdx.x;
    int v = (i < NN) ? cnt[i] : 0;
    sh[threadIdx.x] = v;
    __syncthreads();
    for (int o = 1; o < SCAN_BS; o <<= 1) {
        int t = (threadIdx.x >= o) ? sh[threadIdx.x - o] : 0;
        __syncthreads();
        sh[threadIdx.x] += t;
        __syncthreads();
    }
    if (i <= NN) off[i] = bsum[blockIdx.x] + sh[threadIdx.x] - v;
}
__global__ void k_copy_i(const int* __restrict__ a, int* __restrict__ b, int n) {
    int i = blockIdx.x * blockDim.x + threadIdx.x;
    if (i < n) b[i] = a[i];
}
__global__ void k_bucket(const int* __restrict__ src, const int* __restrict__ dst,
                         const float* __restrict__ dinv, int* __restrict__ cur,
                         int* __restrict__ cs, float* __restrict__ cw) {
    int t = blockIdx.x * blockDim.x + threadIdx.x;
    if (t >= NE2) return;
    int s, d;
    if (t < NE) { s = src[t]; d = dst[t]; }
    else        { s = d = t - NE; }
    int pos = atomicAdd(&cur[d], 1);
    cs[pos] = s;
    cw[pos] = dinv[s] * dinv[d];
}

// ---------------- mma.sync bf16x3 GEMM, K-tile 64, single buffer ----------------
// Block 128x128, 8 warps (4 M x 2 N), warp tile 32x64, K-tile 64 (4 x k16).
// Dynamic smem: 4 planes x 128 rows x 144 B = 73728 B. Conflict-free
// (row stride 144 B -> ldmatrix phase rows hit banks 4r..4r+3 mod 32).
// EPI: 0 none, 1 GCN2 relu((1-b)A + b*AW) (m==k), 2 relu(AW + bias)
#define LDS_B 144
#define PLANE (128 * LDS_B)
#define GSMEM (4 * PLANE)
template <int EPI>
__global__ __launch_bounds__(256) void gemm_mma(
    const float* __restrict__ A, const __nv_bfloat16* __restrict__ Wt,
    float* __restrict__ C, int n, int m, int k, int mpad, float beta,
    const float* __restrict__ bias) {
    extern __shared__ __align__(16) char smem[];
    char* sAh = smem;
    char* sAl = smem + PLANE;
    char* sBh = smem + 2 * PLANE;
    char* sBl = smem + 3 * PLANE;

    const int tid  = threadIdx.x;
    const int wid  = tid >> 5, lane = tid & 31;
    const int warp_m = wid & 3, warp_n = wid >> 2;
    const int row0 = blockIdx.y * 128;
    const int col0 = blockIdx.x * 128;
    const int planeoff = k * mpad;

    const uint32_t ah_b = smem_u32(sAh), al_b = smem_u32(sAl);
    const uint32_t bh_b = smem_u32(sBh), bl_b = smem_u32(sBl);
    const int lr = lane & 15, lc = lane >> 4;
    const uint32_t a_off = (uint32_t)(warp_m * 32 + lr) * LDS_B + lc * 16;
    const uint32_t b_off = (uint32_t)(warp_n * 64 + lr) * LDS_B + lc * 16;

    float acc[2][8][4];
    #pragma unroll
    for (int i = 0; i < 2; i++)
        #pragma unroll
        for (int j = 0; j < 8; j++)
            #pragma unroll
            for (int r = 0; r < 4; r++) acc[i][j][r] = 0.0f;

    const uint4 Z4 = make_uint4(0, 0, 0, 0);

    for (int kt = 0; kt < mpad; kt += 64) {
        __syncthreads();
        // ---- A tile: 128 rows x 64 cols fp32 -> bf16 hi/lo (8 float4/thread) ----
        #pragma unroll
        for (int i = 0; i < 8; i++) {
            int idx = tid + i * 256;        // 2048 units (128 rows x 16 quads)
            int r = idx >> 4, q = idx & 15;
            int gr = row0 + r, gk = kt + q * 4;
            float4 v = make_float4(0.f, 0.f, 0.f, 0.f);
            if (gr < n && gk < m) v = *(const float4*)&A[(size_t)gr * m + gk];
            __nv_bfloat16 h0 = __float2bfloat16(v.x), h1 = __float2bfloat16(v.y);
            __nv_bfloat16 h2 = __float2bfloat16(v.z), h3 = __float2bfloat16(v.w);
            __nv_bfloat16 l0 = __float2bfloat16(v.x - __bfloat162float(h0));
            __nv_bfloat16 l1 = __float2bfloat16(v.y - __bfloat162float(h1));
            __nv_bfloat16 l2 = __float2bfloat16(v.z - __bfloat162float(h2));
            __nv_bfloat16 l3 = __float2bfloat16(v.w - __bfloat162float(h3));
            __nv_bfloat162 hp0 = {h0, h1}, hp1 = {h2, h3};
            __nv_bfloat162 lp0 = {l0, l1}, lp1 = {l2, l3};
            uint2 uh = make_uint2(*(uint32_t*)&hp0, *(uint32_t*)&hp1);
            uint2 ul = make_uint2(*(uint32_t*)&lp0, *(uint32_t*)&lp1);
            *(uint2*)(sAh + r * LDS_B + q * 8) = uh;
            *(uint2*)(sAl + r * LDS_B + q * 8) = ul;
        }
        // ---- B tile: 128 n-rows x 64 k bf16 (pre-split; 4 uint4/thread/plane) ----
        #pragma unroll
        for (int i = 0; i < 4; i++) {
            int idx = tid + i * 256;        // 1024 units (128 rows x 8 u16s)
            int j = idx >> 3, u = idx & 7;
            int gj = col0 + j;
            uint4 vh = Z4, vl = Z4;
            if (gj < k) {
                size_t g = (size_t)gj * mpad + kt + u * 8;
                vh = *(const uint4*)&Wt[g];
                vl = *(const uint4*)&Wt[planeoff + g];
            }
            *(uint4*)(sBh + j * LDS_B + u * 16) = vh;
            *(uint4*)(sBl + j * LDS_B + u * 16) = vl;
        }
        __syncthreads();

        #pragma unroll
        for (int ks = 0; ks < 4; ks++) {
            const uint32_t kb2 = ks * 32;
            uint32_t ah[2][4], al[2][4], bh[4][4], bl[4][4];
            #pragma unroll
            for (int mt = 0; mt < 2; mt++) {
                ldm_x4(ah[mt], ah_b + a_off + mt * (16 * LDS_B) + kb2);
                ldm_x4(al[mt], al_b + a_off + mt * (16 * LDS_B) + kb2);
            }
            #pragma unroll
            for (int nt = 0; nt < 4; nt++) {
                ldm_x4(bh[nt], bh_b + b_off + nt * (16 * LDS_B) + kb2);
                ldm_x4(bl[nt], bl_b + b_off + nt * (16 * LDS_B) + kb2);
            }
            #pragma unroll
            for (int mt = 0; mt < 2; mt++)
                #pragma unroll
                for (int nt = 0; nt < 4; nt++) {
                    mma16816(acc[mt][nt*2+0], ah[mt], bh[nt][0], bh[nt][2]);
                    mma16816(acc[mt][nt*2+1], ah[mt], bh[nt][1], bh[nt][3]);
                    mma16816(acc[mt][nt*2+0], ah[mt], bl[nt][0], bl[nt][2]);
                    mma16816(acc[mt][nt*2+1], ah[mt], bl[nt][1], bl[nt][3]);
                    mma16816(acc[mt][nt*2+0], al[mt], bh[nt][0], bh[nt][2]);
                    mma16816(acc[mt][nt*2+1], al[mt], bh[nt][1], bh[nt][3]);
                }
        }
    }

    // ---- epilogue ----
    const int g = lane >> 2, t = lane & 3;
    #pragma unroll
    for (int mt = 0; mt < 2; mt++) {
        #pragma unroll
        for (int ntg = 0; ntg < 8; ntg++) {
            int gc = col0 + warp_n * 64 + ntg * 8 + t * 2;
            if (gc >= k) continue;
            #pragma unroll
            for (int half = 0; half < 2; half++) {
                int gr = row0 + warp_m * 32 + mt * 16 + g + half * 8;
                if (gr >= n) continue;
                float c0 = acc[mt][ntg][half * 2 + 0];
                float c1 = acc[mt][ntg][half * 2 + 1];
                if (EPI == 1) {
                    float2 x0 = *(const float2*)&A[(size_t)gr * m + gc];
                    c0 = fmaxf(beta * c0 + (1.0f - beta) * x0.x, 0.f);
                    c1 = fmaxf(beta * c1 + (1.0f - beta) * x0.y, 0.f);
                } else if (EPI == 2) {
                    float2 b = *(const float2*)&bias[gc];
                    c0 = fmaxf(c0 + b.x, 0.f);
                    c1 = fmaxf(c1 + b.y, 0.f);
                }
                *(float2*)&C[(size_t)gr * k + gc] = make_float2(c0, c1);
            }
        }
    }
}

// ---------------- pull-based GCN propagation (unroll 4) ----------------
template <int D4, int MODE>
__global__ void prop_pull(const float4* __restrict__ h, float4* __restrict__ o,
                          const float* __restrict__ aux,
                          const int* __restrict__ off, const int* __restrict__ csr_s,
                          const float* __restrict__ csr_w) {
    constexpr int TPN = (D4 < 32) ? D4 : 32;
    constexpr int NPW = 32 / TPN;
    constexpr int R   = D4 / TPN;
    int gwarp = (blockIdx.x * blockDim.x + threadIdx.x) >> 5;
    int lane  = threadIdx.x & 31;
    int node  = gwarp * NPW + lane / TPN;
    int tl    = lane % TPN;
    if (node >= NN) return;

    float4 acc[R];
    #pragma unroll
    for (int r = 0; r < R; r++) acc[r] = make_float4(0.f, 0.f, 0.f, 0.f);

    int j0 = off[node], j1 = off[node + 1];
    int j = j0;
    for (; j + 3 < j1; j += 4) {
        int   s0 = csr_s[j],   s1 = csr_s[j+1], s2 = csr_s[j+2], s3 = csr_s[j+3];
        float w0 = csr_w[j],   w1 = csr_w[j+1], w2 = csr_w[j+2], w3 = csr_w[j+3];
        #pragma unroll
        for (int r = 0; r < R; r++) {
            float4 v0 = h[(size_t)s0 * D4 + tl + r * TPN];
            float4 v1 = h[(size_t)s1 * D4 + tl + r * TPN];
            float4 v2 = h[(size_t)s2 * D4 + tl + r * TPN];
            float4 v3 = h[(size_t)s3 * D4 + tl + r * TPN];
            acc[r].x += w0*v0.x + w1*v1.x + w2*v2.x + w3*v3.x;
            acc[r].y += w0*v0.y + w1*v1.y + w2*v2.y + w3*v3.y;
            acc[r].z += w0*v0.z + w1*v1.z + w2*v2.z + w3*v3.z;
            acc[r].w += w0*v0.w + w1*v1.w + w2*v2.w + w3*v3.w;
        }
    }
    for (; j < j1; j++) {
        int s0 = csr_s[j];
        float w0 = csr_w[j];
        #pragma unroll
        for (int r = 0; r < R; r++) {
            float4 v0 = h[(size_t)s0 * D4 + tl + r * TPN];
            acc[r].x += w0 * v0.x; acc[r].y += w0 * v0.y;
            acc[r].z += w0 * v0.z; acc[r].w += w0 * v0.w;
        }
    }

    const float4* aux4 = (const float4*)aux;
    #pragma unroll
    for (int r = 0; r < R; r++) {
        int c = tl + r * TPN;
        float4 v = acc[r];
        if (MODE == 0 || MODE == 2) {
            float4 b = aux4[c];
            v.x += b.x; v.y += b.y; v.z += b.z; v.w += b.w;
            if (MODE == 0) {
                v.x = fmaxf(v.x, 0.f); v.y = fmaxf(v.y, 0.f);
                v.z = fmaxf(v.z, 0.f); v.w = fmaxf(v.w, 0.f);
            }
        } else if (MODE == 1) {
            float4 x0 = aux4[(size_t)node * D4 + c];
            v.x = 0.5f * (v.x + x0.x); v.y = 0.5f * (v.y + x0.y);
            v.z = 0.5f * (v.z + x0.z); v.w = 0.5f * (v.w + x0.w);
        }
        o[(size_t)node * D4 + c] = v;
    }
}

// ---------------- GATv2: fused flash-softmax, 2-edge unrolled ----------------
__global__ void gat_fused(const float4* __restrict__ xl4, const float4* __restrict__ xr4,
                          const int* __restrict__ off, const int* __restrict__ cs,
                          const float4* __restrict__ att4, const float* __restrict__ bg,
                          float4* __restrict__ out) {
    int node = (blockIdx.x * blockDim.x + threadIdx.x) >> 5;
    int lane = threadIdx.x & 31;
    if (node >= NN) return;
    int j0 = off[node], j1 = off[node + 1];

    float4 xr = xr4[(size_t)node * 32 + lane];
    float4 at = att4[lane];

    float m = -1e30f, s = 0.0f;
    float4 acc = make_float4(0.f, 0.f, 0.f, 0.f);

    int j = j0;
    for (; j + 1 < j1; j += 2) {
        int sa = cs[j], sb = cs[j + 1];
        float4 va = xl4[(size_t)sa * 32 + lane];
        float4 vb = xl4[(size_t)sb * 32 + lane];
        float a0 = va.x + xr.x; a0 = (a0 > 0.f) ? a0 : 0.2f * a0;
        float a1 = va.y + xr.y; a1 = (a1 > 0.f) ? a1 : 0.2f * a1;
        float a2 = va.z + xr.z; a2 = (a2 > 0.f) ? a2 : 0.2f * a2;
        float a3 = va.w + xr.w; a3 = (a3 > 0.f) ? a3 : 0.2f * a3;
        float b0 = vb.x + xr.x; b0 = (b0 > 0.f) ? b0 : 0.2f * b0;
        float b1 = vb.y + xr.y; b1 = (b1 > 0.f) ? b1 : 0.2f * b1;
        float b2 = vb.z + xr.z; b2 = (b2 > 0.f) ? b2 : 0.2f * b2;
        float b3 = vb.w + xr.w; b3 = (b3 > 0.f) ? b3 : 0.2f * b3;
        float pa = a0 * at.x + a1 * at.y + a2 * at.z + a3 * at.w;
        float pb = b0 * at.x + b1 * at.y + b2 * at.z + b3 * at.w;
        pa += __shfl_xor_sync(0xffffffffu, pa, 1);
        pb += __shfl_xor_sync(0xffffffffu, pb, 1);
        pa += __shfl_xor_sync(0xffffffffu, pa, 2);
        pb += __shfl_xor_sync(0xffffffffu, pb, 2);
        pa += __shfl_xor_sync(0xffffffffu, pa, 4);
        pb += __shfl_xor_sync(0xffffffffu, pb, 4);
        float nm = fmaxf(m, fmaxf(pa, pb));
        float r  = __expf(m - nm);
        float wa = __expf(pa - nm);
        float wb = __expf(pb - nm);
        s = s * r + wa + wb;
        acc.x = acc.x * r + wa * va.x + wb * vb.x;
        acc.y = acc.y * r + wa * va.y + wb * vb.y;
        acc.z = acc.z * r + wa * va.z + wb * vb.z;
        acc.w = acc.w * r + wa * va.w + wb * vb.w;
        m = nm;
    }
    if (j < j1) {
        int sn = cs[j];
        float4 v = xl4[(size_t)sn * 32 + lane];
        float e0 = v.x + xr.x; e0 = (e0 > 0.f) ? e0 : 0.2f * e0;
        float e1 = v.y + xr.y; e1 = (e1 > 0.f) ? e1 : 0.2f * e1;
        float e2 = v.z + xr.z; e2 = (e2 > 0.f) ? e2 : 0.2f * e2;
        float e3 = v.w + xr.w; e3 = (e3 > 0.f) ? e3 : 0.2f * e3;
        float p = e0 * at.x + e1 * at.y + e2 * at.z + e3 * at.w;
        p += __shfl_xor_sync(0xffffffffu, p, 1);
        p += __shfl_xor_sync(0xffffffffu, p, 2);
        p += __shfl_xor_sync(0xffffffffu, p, 4);
        float nm = fmaxf(m, p);
        float r  = __expf(m - nm);
        float w  = __expf(p - nm);
        s = s * r + w;
        acc.x = acc.x * r + w * v.x;
        acc.y = acc.y * r + w * v.y;
        acc.z = acc.z * r + w * v.z;
        acc.w = acc.w * r + w * v.w;
        m = nm;
    }
    float inv = 1.0f / (s + 1e-16f);
    float4 b = ((const float4*)bg)[lane];
    acc.x = fmaxf(acc.x * inv + b.x, 0.f);
    acc.y = fmaxf(acc.y * inv + b.y, 0.f);
    acc.z = fmaxf(acc.z * inv + b.z, 0.f);
    acc.w = fmaxf(acc.w * inv + b.w, 0.f);
    out[(size_t)node * 32 + lane] = acc;
}

// ---------------- host helpers ----------------
static inline int mpad64(int m) { return ((m + 63) / 64) * 64; }

static void gemm(const float* A, const __nv_bfloat16* Wt, float* C,
                 int n, int m, int k, int epi, float beta, const float* bias,
                 cudaStream_t st) {
    int mp = mpad64(m);
    dim3 grid(divup(k, 128), divup(n, 128));
    if (epi == 1)      gemm_mma<1><<<grid, 256, GSMEM, st>>>(A, Wt, C, n, m, k, mp, beta, nullptr);
    else if (epi == 2) gemm_mma<2><<<grid, 256, GSMEM, st>>>(A, Wt, C, n, m, k, mp, 0.0f, bias);
    else               gemm_mma<0><<<grid, 256, GSMEM, st>>>(A, Wt, C, n, m, k, mp, 0.0f, nullptr);
}

template <int D4, int MODE>
static void prop_launch(const float* h, float* o, const float* aux,
                        const int* off, const int* cs, const float* cw) {
    constexpr int NPW = (D4 < 32) ? (32 / D4) : 1;
    int warps = divup(NN, NPW);
    prop_pull<D4, MODE><<<divup((long long)warps * 32, 256), 256>>>(
        (const float4*)h, (float4*)o, aux, off, cs, cw);
}

static cudaStream_t s_side = nullptr;
static cudaEvent_t  s_ev0, s_ev1, s_ev2, s_ev3;

// weight offsets (hi-plane element units; each slot holds 2 planes), mpad64
#define WOFF_W1  0
#define WOFF_W2  (WOFF_W1  + 2 * 256 * 320)
#define WOFF_W3  (WOFF_W2  + 2 * 128 * 256)
#define WOFF_W4  (WOFF_W3  + 2 * 64 * 128)
#define WOFF_WL  (WOFF_W4  + 2 * 32 * 64)
#define WOFF_WR  (WOFF_WL  + 2 * 128 * 64)
#define WOFF_WC1 (WOFF_WR  + 2 * 128 * 64)
#define WOFF_W5  (WOFF_WC1 + 2 * 128 * 128)
#define WOFF_WC2 (WOFF_W5  + 2 * 256 * 128)
#define WOFF_WO  (WOFF_WC2 + 2 * 256 * 256)

extern "C" void kernel_launch(void* const* d_in, const int* in_sizes, int n_in,
                              void* d_out, int out_size) {
    if (!s_side) {
        cudaStreamCreateWithFlags(&s_side, cudaStreamNonBlocking);
        cudaEventCreateWithFlags(&s_ev0, cudaEventDisableTiming);
        cudaEventCreateWithFlags(&s_ev1, cudaEventDisableTiming);
        cudaEventCreateWithFlags(&s_ev2, cudaEventDisableTiming);
        cudaEventCreateWithFlags(&s_ev3, cudaEventDisableTiming);
        cudaFuncSetAttribute(gemm_mma<0>, cudaFuncAttributeMaxDynamicSharedMemorySize, GSMEM);
        cudaFuncSetAttribute(gemm_mma<1>, cudaFuncAttributeMaxDynamicSharedMemorySize, GSMEM);
        cudaFuncSetAttribute(gemm_mma<2>, cudaFuncAttributeMaxDynamicSharedMemorySize, GSMEM);
    }
    const cudaStream_t MAIN = 0;

    const float* x   = (const float*)d_in[0];
    const int*   ei32= (const int*)d_in[1];
    const float* W1 = (const float*)d_in[2];  const float* b1 = (const float*)d_in[3];
    const float* W2 = (const float*)d_in[4];  const float* b2 = (const float*)d_in[5];
    const float* W3 = (const float*)d_in[6];  const float* b3 = (const float*)d_in[7];
    const float* W4 = (const float*)d_in[8];  const float* b4 = (const float*)d_in[9];
    const float* Wl = (const float*)d_in[10]; const float* Wr = (const float*)d_in[11];
    const float* att= (const float*)d_in[12]; const float* bg = (const float*)d_in[13];
    const float* Wc1= (const float*)d_in[14];
    const float* W5 = (const float*)d_in[15]; const float* b5 = (const float*)d_in[16];
    const float* Wc2= (const float*)d_in[17];
    const float* Wo = (const float*)d_in[18]; const float* bo = (const float*)d_in[19];
    float* out = (float*)d_out;

    float *x1, *x2, *A, *B, *C, *D, *dinv, *cw;
    int *src, *dst, *cnt, *off, *cur, *bsum, *cs;
    __nv_bfloat16* wt;
    cudaGetSymbolAddress((void**)&x1,   g_x1);
    cudaGetSymbolAddress((void**)&x2,   g_x2);
    cudaGetSymbolAddress((void**)&A,    g_A);
    cudaGetSymbolAddress((void**)&B,    g_B);
    cudaGetSymbolAddress((void**)&C,    g_C);
    cudaGetSymbolAddress((void**)&D,    g_D);
    cudaGetSymbolAddress((void**)&dinv, g_dinv);
    cudaGetSymbolAddress((void**)&src,  g_src);
    cudaGetSymbolAddress((void**)&dst,  g_dst);
    cudaGetSymbolAddress((void**)&cnt,  g_cnt);
    cudaGetSymbolAddress((void**)&off,  g_off);
    cudaGetSymbolAddress((void**)&cur,  g_cur);
    cudaGetSymbolAddress((void**)&bsum, g_bsum);
    cudaGetSymbolAddress((void**)&cs,   g_csr_s);
    cudaGetSymbolAddress((void**)&cw,   g_csr_w);
    cudaGetSymbolAddress((void**)&wt,   g_wt);

    const float BETA = logf(1.05f);

    // ---- head: detect(1), convert(2), splitW1(3), gemm1(4 <- profiled) ----
    k_detect<<<1, 256>>>(ei32);
    k_convert<<<divup(NE, 256), 256>>>(ei32, src, dst);
    k_splitw<<<divup(256 * 320, 256), 256>>>(W1, wt + WOFF_W1, 300, 256, 320);
    gemm(x, wt + WOFF_W1, A, NN, 300, 256, 0, 0.0f, nullptr, MAIN);
    cudaEventRecord(s_ev0, MAIN);
    cudaStreamWaitEvent(s_side, s_ev0, 0);

    // side stream: remaining weight splits (mpad64) + CSR build
    k_splitw<<<divup(128 * 256, 256), 256, 0, s_side>>>(W2,  wt + WOFF_W2,  256, 128, 256);
    k_splitw<<<divup(64 * 128, 256),  256, 0, s_side>>>(W3,  wt + WOFF_W3,  128, 64, 128);
    k_splitw<<<divup(32 * 64, 256),   256, 0, s_side>>>(W4,  wt + WOFF_W4,  64, 32, 64);
    k_splitw<<<divup(128 * 64, 256),  256, 0, s_side>>>(Wl,  wt + WOFF_WL,  32, 128, 64);
    k_splitw<<<divup(128 * 64, 256),  256, 0, s_side>>>(Wr,  wt + WOFF_WR,  32, 128, 64);
    k_splitw<<<divup(128 * 128, 256), 256, 0, s_side>>>(Wc1, wt + WOFF_WC1, 128, 128, 128);
    k_splitw<<<divup(256 * 128, 256), 256, 0, s_side>>>(W5,  wt + WOFF_W5,  128, 256, 128);
    k_splitw<<<divup(256 * 256, 256), 256, 0, s_side>>>(Wc2, wt + WOFF_WC2, 256, 256, 256);
    k_splitw<<<divup(128 * 256, 256), 256, 0, s_side>>>(Wo,  wt + WOFF_WO,  256, 128, 256);
    k_fill_i<<<divup(NN, 256), 256, 0, s_side>>>(cnt, NN, 1);
    k_count<<<divup(NE, 256), 256, 0, s_side>>>(dst, cnt);
    k_dinv<<<divup(NN, 256), 256, 0, s_side>>>(cnt, dinv);
    scan1<<<SCAN_NB, SCAN_BS, 0, s_side>>>(cnt, bsum);
    scan2<<<1, 1024, 0, s_side>>>(bsum);
    scan3<<<SCAN_NB, SCAN_BS, 0, s_side>>>(cnt, bsum, off);
    k_copy_i<<<divup(NN, 256), 256, 0, s_side>>>(off, cur, NN);
    k_bucket<<<divup(NE2, 256), 256, 0, s_side>>>(src, dst, dinv, cur, cs, cw);
    cudaEventRecord(s_ev1, s_side);
    cudaStreamWaitEvent(MAIN, s_ev1, 0);

    // ---- x1 = relu(prop(x@W1)+b1) ----
    prop_launch<64, 0>(A, x1, b1, off, cs, cw);

    // ---- x2 = relu(prop(x1@W2)+b2) ----
    gemm(x1, wt + WOFF_W2, A, NN, 256, 128, 0, 0.0f, nullptr, MAIN);
    prop_launch<32, 0>(A, x2, b2, off, cs, cw);

    // ---- x3 = relu(prop(x2@W3)+b3)  (64) ----
    gemm(x2, wt + WOFF_W3, A, NN, 128, 64, 0, 0.0f, nullptr, MAIN);
    prop_launch<16, 0>(A, B, b3, off, cs, cw);

    // ---- x3 = relu(prop(x3@W4)+b4)  (32) ----
    gemm(B, wt + WOFF_W4, A, NN, 64, 32, 0, 0.0f, nullptr, MAIN);
    prop_launch<8, 0>(A, B, b4, off, cs, cw);

    // ---- GATv2 (128); xl=C (main), xr=A (side) — fused flash-softmax ----
    cudaEventRecord(s_ev2, MAIN);
    cudaStreamWaitEvent(s_side, s_ev2, 0);
    gemm(B, wt + WOFF_WR, A, NN, 32, 128, 0, 0.0f, nullptr, s_side);
    cudaEventRecord(s_ev3, s_side);
    gemm(B, wt + WOFF_WL, C, NN, 32, 128, 0, 0.0f, nullptr, MAIN);
    cudaStreamWaitEvent(MAIN, s_ev3, 0);
    gat_fused<<<divup((long long)NN * 32, 256), 256>>>(
        (const float4*)C, (const float4*)A, off, cs,
        (const float4*)att, bg, (float4*)D);

    // ---- GCN2 #1 with x0=x2 (128) ----
    prop_launch<32, 1>(D, A, x2, off, cs, cw);
    gemm(A, wt + WOFF_WC1, B, NN, 128, 128, 1, BETA, nullptr, MAIN);

    // ---- x3 = relu(prop(B)@W5 + b5)  (prop commuted to 128-d) ----
    prop_launch<32, 3>(B, A, nullptr, off, cs, cw);
    gemm(A, wt + WOFF_W5, C, NN, 128, 256, 2, 0.0f, b5, MAIN);

    // ---- GCN2 #2 with x0=x1 (256) ----
    prop_launch<64, 1>(C, A, x1, off, cs, cw);
    gemm(A, wt + WOFF_WC2, B, NN, 256, 256, 1, BETA, nullptr, MAIN);

    // ---- out = prop(x3@Wo) + bo ----
    gemm(B, wt + WOFF_WO, A, NN, 256, 128, 0, 0.0f, nullptr, MAIN);
    prop_launch<32, 2>(A, out, bo, off, cs, cw);
}

// round 17
// speedup vs baseline: 1.1180x; 1.0025x over previous
#include <cuda_runtime.h>
#include <cuda_bf16.h>
#include <cstdint>
#include <math.h>

#define NN 50000
#define NE 800000
#define NE2 850000
#define NE2P 1001472   /* padded CSR capacity: NE2 + 3*NN + slack */
#define SCAN_BS 512
#define SCAN_NB ((NN + SCAN_BS - 1) / SCAN_BS)

// ---------------- device scratch ----------------
__device__ __align__(16) float g_x1[(size_t)NN * 256];
__device__ __align__(16) float g_x2[(size_t)NN * 128];
__device__ __align__(16) float g_A [(size_t)NN * 256];
__device__ __align__(16) float g_B [(size_t)NN * 256];
__device__ __align__(16) float g_C [(size_t)NN * 256];
__device__ __align__(16) float g_D [(size_t)NN * 128];
__device__ float    g_dinv[NN];
__device__ int      g_src[NE];
__device__ int      g_dst[NE];
__device__ int      g_cnt[NN];
__device__ int      g_off[NN + 1];
__device__ int      g_cur[NN];
__device__ int      g_bsum[SCAN_NB + 32];
__device__ __align__(16) int   g_csr_s[NE2P];
__device__ __align__(16) float g_csr_w[NE2P];
__device__ int      g_eflag[1];
__device__ __align__(16) __nv_bfloat16 g_wt[600000];

static inline int divup(long long a, int b) { return (int)((a + b - 1) / b); }

// ---------------- PTX helpers (plain-sm_100 legal) ----------------
__device__ __forceinline__ uint32_t smem_u32(const void* p) {
    uint32_t a;
    asm("{ .reg .u64 t; cvta.to.shared.u64 t, %1; cvt.u32.u64 %0, t; }" : "=r"(a) : "l"(p));
    return a;
}
__device__ __forceinline__ void ldm_x4(uint32_t (&r)[4], uint32_t addr) {
    asm volatile("ldmatrix.sync.aligned.m8n8.x4.shared.b16 {%0,%1,%2,%3}, [%4];"
                 : "=r"(r[0]), "=r"(r[1]), "=r"(r[2]), "=r"(r[3]) : "r"(addr));
}
__device__ __forceinline__ void mma16816(float (&d)[4], const uint32_t (&a)[4],
                                         uint32_t b0, uint32_t b1) {
    asm volatile(
        "mma.sync.aligned.m16n8k16.row.col.f32.bf16.bf16.f32 "
        "{%0,%1,%2,%3}, {%4,%5,%6,%7}, {%8,%9}, {%0,%1,%2,%3};"
        : "+f"(d[0]), "+f"(d[1]), "+f"(d[2]), "+f"(d[3])
        : "r"(a[0]), "r"(a[1]), "r"(a[2]), "r"(a[3]), "r"(b0), "r"(b1));
}

// ---------------- edge-index dtype detection + conversion ----------------
__global__ void k_detect(const int* __restrict__ ei32) {
    __shared__ int cnt;
    if (threadIdx.x == 0) cnt = 0;
    __syncthreads();
    int nz = 0;
    for (int i = threadIdx.x; i < 2048; i += blockDim.x)
        if (ei32[2 * i + 1] != 0) nz++;
    atomicAdd(&cnt, nz);
    __syncthreads();
    if (threadIdx.x == 0) g_eflag[0] = (cnt == 0) ? 1 : 0;
}
__global__ void k_convert(const int* __restrict__ ei32,
                          int* __restrict__ src, int* __restrict__ dst) {
    int e = blockIdx.x * blockDim.x + threadIdx.x;
    if (e >= NE) return;
    int is64 = g_eflag[0];
    int s, d;
    if (is64) { s = ei32[2 * e]; d = ei32[2 * (NE + e)]; }
    else      { s = ei32[e];     d = ei32[NE + e]; }
    s = min(max(s, 0), NN - 1);
    d = min(max(d, 0), NN - 1);
    src[e] = s; dst[e] = d;
}

// ---------------- weight pre-transpose + bf16 split ----------------
__global__ void k_splitw(const float* __restrict__ W, __nv_bfloat16* __restrict__ wt,
                         int m, int k, int mpad) {
    int idx = blockIdx.x * blockDim.x + threadIdx.x;
    int tot = k * mpad;
    if (idx >= tot) return;
    int j = idx / mpad, kk = idx % mpad;
    float f = (kk < m) ? W[(size_t)kk * k + j] : 0.0f;
    __nv_bfloat16 h = __float2bfloat16(f);
    __nv_bfloat16 l = __float2bfloat16(f - __bfloat162float(h));
    wt[idx] = h;
    wt[tot + idx] = l;
}

// ---------------- CSR build (rows padded to multiple of 4) ----------------
__global__ void k_fill_i(int* p, int n, int v) {
    int i = blockIdx.x * blockDim.x + threadIdx.x;
    if (i < n) p[i] = v;
}
__global__ void k_count(const int* __restrict__ dst, int* __restrict__ cnt) {
    int e = blockIdx.x * blockDim.x + threadIdx.x;
    if (e < NE) atomicAdd(&cnt[dst[e]], 1);
}
__global__ void k_dinv(const int* __restrict__ cnt, float* __restrict__ dinv) {
    int i = blockIdx.x * blockDim.x + threadIdx.x;
    if (i < NN) dinv[i] = rsqrtf((float)cnt[i]);
}
__global__ void scan1(const int* __restrict__ cnt, int* __restrict__ bsum) {
    __shared__ int sh[SCAN_BS];
    int i = blockIdx.x * SCAN_BS + threadIdx.x;
    sh[threadIdx.x] = (i < NN) ? ((cnt[i] + 3) & ~3) : 0;
    __syncthreads();
    for (int s = SCAN_BS / 2; s; s >>= 1) {
        if (threadIdx.x < s) sh[threadIdx.x] += sh[threadIdx.x + s];
        __syncthreads();
    }
    if (threadIdx.x == 0) bsum[blockIdx.x] = sh[0];
}
__global__ void scan2(int* __restrict__ bsum) {
    __shared__ int sh[1024];
    int v = (threadIdx.x < SCAN_NB) ? bsum[threadIdx.x] : 0;
    sh[threadIdx.x] = v;
    __syncthreads();
    for (int o = 1; o < 1024; o <<= 1) {
        int t = (threadIdx.x >= o) ? sh[threadIdx.x - o] : 0;
        __syncthreads();
        sh[threadIdx.x] += t;
        __syncthreads();
    }
    if (threadIdx.x < SCAN_NB) bsum[threadIdx.x] = sh[threadIdx.x] - v;
}
__global__ void scan3(const int* __restrict__ cnt, const int* __restrict__ bsum,
                      int* __restrict__ off) {
    __shared__ int sh[SCAN_BS];
    int i = blockIdx.x * SCAN_BS + threadIdx.x;
    int v = (i < NN) ? ((cnt[i] + 3) & ~3) : 0;
    sh[threadIdx.x] = v;
    __syncthreads();
    for (int o = 1; o < SCAN_BS; o <<= 1) {
        int t = (threadIdx.x >= o) ? sh[threadIdx.x - o] : 0;
        __syncthreads();
        sh[threadIdx.x] += t;
        __syncthreads();
    }
    if (i <= NN) off[i] = bsum[blockIdx.x] + sh[threadIdx.x] - v;
}
__global__ void k_copy_i(const int* __restrict__ a, int* __restrict__ b, int n) {
    int i = blockIdx.x * blockDim.x + threadIdx.x;
    if (i < n) b[i] = a[i];
}
__global__ void k_bucket(const int* __restrict__ src, const int* __restrict__ dst,
                         const float* __restrict__ dinv, int* __restrict__ cur,
                         int* __restrict__ cs, float* __restrict__ cw) {
    int t = blockIdx.x * blockDim.x + threadIdx.x;
    if (t >= NE2) return;
    int s, d;
    if (t < NE) { s = src[t]; d = dst[t]; }
    else        { s = d = t - NE; }
    int pos = atomicAdd(&cur[d], 1);
    cs[pos] = s;
    cw[pos] = dinv[s] * dinv[d];
}
__global__ void k_pad(const int* __restrict__ cur, const int* __restrict__ off,
                      int* __restrict__ cs, float* __restrict__ cw) {
    int i = blockIdx.x * blockDim.x + threadIdx.x;
    if (i >= NN) return;
    int p0 = cur[i], p1 = off[i + 1];
    for (int p = p0; p < p1; p++) { cs[p] = -1; cw[p] = 0.0f; }
}

// ---------------- mma.sync bf16x3 GEMM, K-tile 64, single buffer ----------------
#define LDS_B 144
#define PLANE (128 * LDS_B)
#define GSMEM (4 * PLANE)
template <int EPI>
__global__ __launch_bounds__(256) void gemm_mma(
    const float* __restrict__ A, const __nv_bfloat16* __restrict__ Wt,
    float* __restrict__ C, int n, int m, int k, int mpad, float beta,
    const float* __restrict__ bias) {
    extern __shared__ __align__(16) char smem[];
    char* sAh = smem;
    char* sAl = smem + PLANE;
    char* sBh = smem + 2 * PLANE;
    char* sBl = smem + 3 * PLANE;

    const int tid  = threadIdx.x;
    const int wid  = tid >> 5, lane = tid & 31;
    const int warp_m = wid & 3, warp_n = wid >> 2;
    const int row0 = blockIdx.y * 128;
    const int col0 = blockIdx.x * 128;
    const int planeoff = k * mpad;

    const uint32_t ah_b = smem_u32(sAh), al_b = smem_u32(sAl);
    const uint32_t bh_b = smem_u32(sBh), bl_b = smem_u32(sBl);
    const int lr = lane & 15, lc = lane >> 4;
    const uint32_t a_off = (uint32_t)(warp_m * 32 + lr) * LDS_B + lc * 16;
    const uint32_t b_off = (uint32_t)(warp_n * 64 + lr) * LDS_B + lc * 16;

    float acc[2][8][4];
    #pragma unroll
    for (int i = 0; i < 2; i++)
        #pragma unroll
        for (int j = 0; j < 8; j++)
            #pragma unroll
            for (int r = 0; r < 4; r++) acc[i][j][r] = 0.0f;

    const uint4 Z4 = make_uint4(0, 0, 0, 0);

    for (int kt = 0; kt < mpad; kt += 64) {
        __syncthreads();
        #pragma unroll
        for (int i = 0; i < 8; i++) {
            int idx = tid + i * 256;
            int r = idx >> 4, q = idx & 15;
            int gr = row0 + r, gk = kt + q * 4;
            float4 v = make_float4(0.f, 0.f, 0.f, 0.f);
            if (gr < n && gk < m) v = *(const float4*)&A[(size_t)gr * m + gk];
            __nv_bfloat16 h0 = __float2bfloat16(v.x), h1 = __float2bfloat16(v.y);
            __nv_bfloat16 h2 = __float2bfloat16(v.z), h3 = __float2bfloat16(v.w);
            __nv_bfloat16 l0 = __float2bfloat16(v.x - __bfloat162float(h0));
            __nv_bfloat16 l1 = __float2bfloat16(v.y - __bfloat162float(h1));
            __nv_bfloat16 l2 = __float2bfloat16(v.z - __bfloat162float(h2));
            __nv_bfloat16 l3 = __float2bfloat16(v.w - __bfloat162float(h3));
            __nv_bfloat162 hp0 = {h0, h1}, hp1 = {h2, h3};
            __nv_bfloat162 lp0 = {l0, l1}, lp1 = {l2, l3};
            uint2 uh = make_uint2(*(uint32_t*)&hp0, *(uint32_t*)&hp1);
            uint2 ul = make_uint2(*(uint32_t*)&lp0, *(uint32_t*)&lp1);
            *(uint2*)(sAh + r * LDS_B + q * 8) = uh;
            *(uint2*)(sAl + r * LDS_B + q * 8) = ul;
        }
        #pragma unroll
        for (int i = 0; i < 4; i++) {
            int idx = tid + i * 256;
            int j = idx >> 3, u = idx & 7;
            int gj = col0 + j;
            uint4 vh = Z4, vl = Z4;
            if (gj < k) {
                size_t g = (size_t)gj * mpad + kt + u * 8;
                vh = *(const uint4*)&Wt[g];
                vl = *(const uint4*)&Wt[planeoff + g];
            }
            *(uint4*)(sBh + j * LDS_B + u * 16) = vh;
            *(uint4*)(sBl + j * LDS_B + u * 16) = vl;
        }
        __syncthreads();

        #pragma unroll
        for (int ks = 0; ks < 4; ks++) {
            const uint32_t kb2 = ks * 32;
            uint32_t ah[2][4], al[2][4], bh[4][4], bl[4][4];
            #pragma unroll
            for (int mt = 0; mt < 2; mt++) {
                ldm_x4(ah[mt], ah_b + a_off + mt * (16 * LDS_B) + kb2);
                ldm_x4(al[mt], al_b + a_off + mt * (16 * LDS_B) + kb2);
            }
            #pragma unroll
            for (int nt = 0; nt < 4; nt++) {
                ldm_x4(bh[nt], bh_b + b_off + nt * (16 * LDS_B) + kb2);
                ldm_x4(bl[nt], bl_b + b_off + nt * (16 * LDS_B) + kb2);
            }
            #pragma unroll
            for (int mt = 0; mt < 2; mt++)
                #pragma unroll
                for (int nt = 0; nt < 4; nt++) {
                    mma16816(acc[mt][nt*2+0], ah[mt], bh[nt][0], bh[nt][2]);
                    mma16816(acc[mt][nt*2+1], ah[mt], bh[nt][1], bh[nt][3]);
                    mma16816(acc[mt][nt*2+0], ah[mt], bl[nt][0], bl[nt][2]);
                    mma16816(acc[mt][nt*2+1], ah[mt], bl[nt][1], bl[nt][3]);
                    mma16816(acc[mt][nt*2+0], al[mt], bh[nt][0], bh[nt][2]);
                    mma16816(acc[mt][nt*2+1], al[mt], bh[nt][1], bh[nt][3]);
                }
        }
    }

    const int g = lane >> 2, t = lane & 3;
    #pragma unroll
    for (int mt = 0; mt < 2; mt++) {
        #pragma unroll
        for (int ntg = 0; ntg < 8; ntg++) {
            int gc = col0 + warp_n * 64 + ntg * 8 + t * 2;
            if (gc >= k) continue;
            #pragma unroll
            for (int half = 0; half < 2; half++) {
                int gr = row0 + warp_m * 32 + mt * 16 + g + half * 8;
                if (gr >= n) continue;
                float c0 = acc[mt][ntg][half * 2 + 0];
                float c1 = acc[mt][ntg][half * 2 + 1];
                if (EPI == 1) {
                    float2 x0 = *(const float2*)&A[(size_t)gr * m + gc];
                    c0 = fmaxf(beta * c0 + (1.0f - beta) * x0.x, 0.f);
                    c1 = fmaxf(beta * c1 + (1.0f - beta) * x0.y, 0.f);
                } else if (EPI == 2) {
                    float2 b = *(const float2*)&bias[gc];
                    c0 = fmaxf(c0 + b.x, 0.f);
                    c1 = fmaxf(c1 + b.y, 0.f);
                }
                *(float2*)&C[(size_t)gr * k + gc] = make_float2(c0, c1);
            }
        }
    }
}

// ---------------- pull-based GCN propagation (padded CSR, vector index loads) ----------------
template <int D4, int MODE>
__global__ void prop_pull(const float4* __restrict__ h, float4* __restrict__ o,
                          const float* __restrict__ aux,
                          const int* __restrict__ off, const int* __restrict__ csr_s,
                          const float* __restrict__ csr_w) {
    constexpr int TPN = (D4 < 32) ? D4 : 32;
    constexpr int NPW = 32 / TPN;
    constexpr int R   = D4 / TPN;
    int gwarp = (blockIdx.x * blockDim.x + threadIdx.x) >> 5;
    int lane  = threadIdx.x & 31;
    int node  = gwarp * NPW + lane / TPN;
    int tl    = lane % TPN;
    if (node >= NN) return;

    float4 acc[R];
    #pragma unroll
    for (int r = 0; r < R; r++) acc[r] = make_float4(0.f, 0.f, 0.f, 0.f);

    int j0 = off[node], j1 = off[node + 1];
    for (int j = j0; j < j1; j += 4) {
        int4   s4 = *(const int4*)&csr_s[j];
        float4 w4 = *(const float4*)&csr_w[j];
        int s0 = max(s4.x, 0), s1 = max(s4.y, 0), s2 = max(s4.z, 0), s3 = max(s4.w, 0);
        #pragma unroll
        for (int r = 0; r < R; r++) {
            float4 v0 = h[(size_t)s0 * D4 + tl + r * TPN];
            float4 v1 = h[(size_t)s1 * D4 + tl + r * TPN];
            float4 v2 = h[(size_t)s2 * D4 + tl + r * TPN];
            float4 v3 = h[(size_t)s3 * D4 + tl + r * TPN];
            acc[r].x += w4.x*v0.x + w4.y*v1.x + w4.z*v2.x + w4.w*v3.x;
            acc[r].y += w4.x*v0.y + w4.y*v1.y + w4.z*v2.y + w4.w*v3.y;
            acc[r].z += w4.x*v0.z + w4.y*v1.z + w4.z*v2.z + w4.w*v3.z;
            acc[r].w += w4.x*v0.w + w4.y*v1.w + w4.z*v2.w + w4.w*v3.w;
        }
    }

    const float4* aux4 = (const float4*)aux;
    #pragma unroll
    for (int r = 0; r < R; r++) {
        int c = tl + r * TPN;
        float4 v = acc[r];
        if (MODE == 0 || MODE == 2) {
            float4 b = aux4[c];
            v.x += b.x; v.y += b.y; v.z += b.z; v.w += b.w;
            if (MODE == 0) {
                v.x = fmaxf(v.x, 0.f); v.y = fmaxf(v.y, 0.f);
                v.z = fmaxf(v.z, 0.f); v.w = fmaxf(v.w, 0.f);
            }
        } else if (MODE == 1) {
            float4 x0 = aux4[(size_t)node * D4 + c];
            v.x = 0.5f * (v.x + x0.x); v.y = 0.5f * (v.y + x0.y);
            v.z = 0.5f * (v.z + x0.z); v.w = 0.5f * (v.w + x0.w);
        }
        o[(size_t)node * D4 + c] = v;
    }
}

// ---------------- GATv2: fused flash-softmax, 2-edge unrolled, padded CSR ----------------
__global__ void gat_fused(const float4* __restrict__ xl4, const float4* __restrict__ xr4,
                          const int* __restrict__ off, const int* __restrict__ cs,
                          const float4* __restrict__ att4, const float* __restrict__ bg,
                          float4* __restrict__ out) {
    int node = (blockIdx.x * blockDim.x + threadIdx.x) >> 5;
    int lane = threadIdx.x & 31;
    if (node >= NN) return;
    int j0 = off[node], j1 = off[node + 1];

    float4 xr = xr4[(size_t)node * 32 + lane];
    float4 at = att4[lane];

    float m = -1e30f, s = 0.0f;
    float4 acc = make_float4(0.f, 0.f, 0.f, 0.f);

    for (int j = j0; j < j1; j += 2) {
        int2 sp = *(const int2*)&cs[j];
        int sa = max(sp.x, 0), sb = max(sp.y, 0);
        float4 va = xl4[(size_t)sa * 32 + lane];
        float4 vb = xl4[(size_t)sb * 32 + lane];
        float a0 = va.x + xr.x; a0 = (a0 > 0.f) ? a0 : 0.2f * a0;
        float a1 = va.y + xr.y; a1 = (a1 > 0.f) ? a1 : 0.2f * a1;
        float a2 = va.z + xr.z; a2 = (a2 > 0.f) ? a2 : 0.2f * a2;
        float a3 = va.w + xr.w; a3 = (a3 > 0.f) ? a3 : 0.2f * a3;
        float b0 = vb.x + xr.x; b0 = (b0 > 0.f) ? b0 : 0.2f * b0;
        float b1 = vb.y + xr.y; b1 = (b1 > 0.f) ? b1 : 0.2f * b1;
        float b2 = vb.z + xr.z; b2 = (b2 > 0.f) ? b2 : 0.2f * b2;
        float b3 = vb.w + xr.w; b3 = (b3 > 0.f) ? b3 : 0.2f * b3;
        float pa = a0 * at.x + a1 * at.y + a2 * at.z + a3 * at.w;
        float pb = b0 * at.x + b1 * at.y + b2 * at.z + b3 * at.w;
        pa += __shfl_xor_sync(0xffffffffu, pa, 1);
        pb += __shfl_xor_sync(0xffffffffu, pb, 1);
        pa += __shfl_xor_sync(0xffffffffu, pa, 2);
        pb += __shfl_xor_sync(0xffffffffu, pb, 2);
        pa += __shfl_xor_sync(0xffffffffu, pa, 4);
        pb += __shfl_xor_sync(0xffffffffu, pb, 4);
        if (sp.x < 0) pa = -1e30f;
        if (sp.y < 0) pb = -1e30f;
        float nm = fmaxf(m, fmaxf(pa, pb));
        float r  = __expf(m - nm);
        float wa = __expf(pa - nm);
        float wb = __expf(pb - nm);
        s = s * r + wa + wb;
        acc.x = acc.x * r + wa * va.x + wb * vb.x;
        acc.y = acc.y * r + wa * va.y + wb * vb.y;
        acc.z = acc.z * r + wa * va.z + wb * vb.z;
        acc.w = acc.w * r + wa * va.w + wb * vb.w;
        m = nm;
    }
    float inv = 1.0f / (s + 1e-16f);
    float4 b = ((const float4*)bg)[lane];
    acc.x = fmaxf(acc.x * inv + b.x, 0.f);
    acc.y = fmaxf(acc.y * inv + b.y, 0.f);
    acc.z = fmaxf(acc.z * inv + b.z, 0.f);
    acc.w = fmaxf(acc.w * inv + b.w, 0.f);
    out[(size_t)node * 32 + lane] = acc;
}

// ---------------- host helpers ----------------
static inline int mpad64(int m) { return ((m + 63) / 64) * 64; }

static void gemm(const float* A, const __nv_bfloat16* Wt, float* C,
                 int n, int m, int k, int epi, float beta, const float* bias,
                 cudaStream_t st) {
    int mp = mpad64(m);
    dim3 grid(divup(k, 128), divup(n, 128));
    if (epi == 1)      gemm_mma<1><<<grid, 256, GSMEM, st>>>(A, Wt, C, n, m, k, mp, beta, nullptr);
    else if (epi == 2) gemm_mma<2><<<grid, 256, GSMEM, st>>>(A, Wt, C, n, m, k, mp, 0.0f, bias);
    else               gemm_mma<0><<<grid, 256, GSMEM, st>>>(A, Wt, C, n, m, k, mp, 0.0f, nullptr);
}

template <int D4, int MODE>
static void prop_launch(const float* h, float* o, const float* aux,
                        const int* off, const int* cs, const float* cw) {
    constexpr int NPW = (D4 < 32) ? (32 / D4) : 1;
    int warps = divup(NN, NPW);
    prop_pull<D4, MODE><<<divup((long long)warps * 32, 256), 256>>>(
        (const float4*)h, (float4*)o, aux, off, cs, cw);
}

static cudaStream_t s_side = nullptr;
static cudaEvent_t  s_ev0, s_ev1, s_ev2, s_ev3;

#define WOFF_W1  0
#define WOFF_W2  (WOFF_W1  + 2 * 256 * 320)
#define WOFF_W3  (WOFF_W2  + 2 * 128 * 256)
#define WOFF_W4  (WOFF_W3  + 2 * 64 * 128)
#define WOFF_WL  (WOFF_W4  + 2 * 32 * 64)
#define WOFF_WR  (WOFF_WL  + 2 * 128 * 64)
#define WOFF_WC1 (WOFF_WR  + 2 * 128 * 64)
#define WOFF_W5  (WOFF_WC1 + 2 * 128 * 128)
#define WOFF_WC2 (WOFF_W5  + 2 * 256 * 128)
#define WOFF_WO  (WOFF_WC2 + 2 * 256 * 256)

extern "C" void kernel_launch(void* const* d_in, const int* in_sizes, int n_in,
                              void* d_out, int out_size) {
    if (!s_side) {
        cudaStreamCreateWithFlags(&s_side, cudaStreamNonBlocking);
        cudaEventCreateWithFlags(&s_ev0, cudaEventDisableTiming);
        cudaEventCreateWithFlags(&s_ev1, cudaEventDisableTiming);
        cudaEventCreateWithFlags(&s_ev2, cudaEventDisableTiming);
        cudaEventCreateWithFlags(&s_ev3, cudaEventDisableTiming);
        cudaFuncSetAttribute(gemm_mma<0>, cudaFuncAttributeMaxDynamicSharedMemorySize, GSMEM);
        cudaFuncSetAttribute(gemm_mma<1>, cudaFuncAttributeMaxDynamicSharedMemorySize, GSMEM);
        cudaFuncSetAttribute(gemm_mma<2>, cudaFuncAttributeMaxDynamicSharedMemorySize, GSMEM);
    }
    const cudaStream_t MAIN = 0;

    const float* x   = (const float*)d_in[0];
    const int*   ei32= (const int*)d_in[1];
    const float* W1 = (const float*)d_in[2];  const float* b1 = (const float*)d_in[3];
    const float* W2 = (const float*)d_in[4];  const float* b2 = (const float*)d_in[5];
    const float* W3 = (const float*)d_in[6];  const float* b3 = (const float*)d_in[7];
    const float* W4 = (const float*)d_in[8];  const float* b4 = (const float*)d_in[9];
    const float* Wl = (const float*)d_in[10]; const float* Wr = (const float*)d_in[11];
    const float* att= (const float*)d_in[12]; const float* bg = (const float*)d_in[13];
    const float* Wc1= (const float*)d_in[14];
    const float* W5 = (const float*)d_in[15]; const float* b5 = (const float*)d_in[16];
    const float* Wc2= (const float*)d_in[17];
    const float* Wo = (const float*)d_in[18]; const float* bo = (const float*)d_in[19];
    float* out = (float*)d_out;

    float *x1, *x2, *A, *B, *C, *D, *dinv, *cw;
    int *src, *dst, *cnt, *off, *cur, *bsum, *cs;
    __nv_bfloat16* wt;
    cudaGetSymbolAddress((void**)&x1,   g_x1);
    cudaGetSymbolAddress((void**)&x2,   g_x2);
    cudaGetSymbolAddress((void**)&A,    g_A);
    cudaGetSymbolAddress((void**)&B,    g_B);
    cudaGetSymbolAddress((void**)&C,    g_C);
    cudaGetSymbolAddress((void**)&D,    g_D);
    cudaGetSymbolAddress((void**)&dinv, g_dinv);
    cudaGetSymbolAddress((void**)&src,  g_src);
    cudaGetSymbolAddress((void**)&dst,  g_dst);
    cudaGetSymbolAddress((void**)&cnt,  g_cnt);
    cudaGetSymbolAddress((void**)&off,  g_off);
    cudaGetSymbolAddress((void**)&cur,  g_cur);
    cudaGetSymbolAddress((void**)&bsum, g_bsum);
    cudaGetSymbolAddress((void**)&cs,   g_csr_s);
    cudaGetSymbolAddress((void**)&cw,   g_csr_w);
    cudaGetSymbolAddress((void**)&wt,   g_wt);

    const float BETA = logf(1.05f);

    // ---- head: splitW1(#1 MAIN) -> fork -> side(detect/convert/CSR) ; gemm1 on MAIN ----
    k_splitw<<<divup(256 * 320, 256), 256>>>(W1, wt + WOFF_W1, 300, 256, 320);
    cudaEventRecord(s_ev0, MAIN);                 // fork point (capture-legal)
    cudaStreamWaitEvent(s_side, s_ev0, 0);
    k_detect<<<1, 256, 0, s_side>>>(ei32);
    k_convert<<<divup(NE, 256), 256, 0, s_side>>>(ei32, src, dst);
    gemm(x, wt + WOFF_W1, A, NN, 300, 256, 0, 0.0f, nullptr, MAIN);

    // side stream: remaining weight splits (mpad64) + CSR build (padded)
    k_splitw<<<divup(128 * 256, 256), 256, 0, s_side>>>(W2,  wt + WOFF_W2,  256, 128, 256);
    k_splitw<<<divup(64 * 128, 256),  256, 0, s_side>>>(W3,  wt + WOFF_W3,  128, 64, 128);
    k_splitw<<<divup(32 * 64, 256),   256, 0, s_side>>>(W4,  wt + WOFF_W4,  64, 32, 64);
    k_splitw<<<divup(128 * 64, 256),  256, 0, s_side>>>(Wl,  wt + WOFF_WL,  32, 128, 64);
    k_splitw<<<divup(128 * 64, 256),  256, 0, s_side>>>(Wr,  wt + WOFF_WR,  32, 128, 64);
    k_splitw<<<divup(128 * 128, 256), 256, 0, s_side>>>(Wc1, wt + WOFF_WC1, 128, 128, 128);
    k_splitw<<<divup(256 * 128, 256), 256, 0, s_side>>>(W5,  wt + WOFF_W5,  128, 256, 128);
    k_splitw<<<divup(256 * 256, 256), 256, 0, s_side>>>(Wc2, wt + WOFF_WC2, 256, 256, 256);
    k_splitw<<<divup(128 * 256, 256), 256, 0, s_side>>>(Wo,  wt + WOFF_WO,  256, 128, 256);
    k_fill_i<<<divup(NN, 256), 256, 0, s_side>>>(cnt, NN, 1);
    k_count<<<divup(NE, 256), 256, 0, s_side>>>(dst, cnt);
    k_dinv<<<divup(NN, 256), 256, 0, s_side>>>(cnt, dinv);
    scan1<<<SCAN_NB, SCAN_BS, 0, s_side>>>(cnt, bsum);
    scan2<<<1, 1024, 0, s_side>>>(bsum);
    scan3<<<SCAN_NB, SCAN_BS, 0, s_side>>>(cnt, bsum, off);
    k_copy_i<<<divup(NN, 256), 256, 0, s_side>>>(off, cur, NN);
    k_bucket<<<divup(NE2, 256), 256, 0, s_side>>>(src, dst, dinv, cur, cs, cw);
    k_pad<<<divup(NN, 256), 256, 0, s_side>>>(cur, off, cs, cw);
    cudaEventRecord(s_ev1, s_side);
    cudaStreamWaitEvent(MAIN, s_ev1, 0);

    // ---- x1 = relu(prop(x@W1)+b1) ----
    prop_launch<64, 0>(A, x1, b1, off, cs, cw);

    // ---- x2 = relu(prop(x1@W2)+b2) ----
    gemm(x1, wt + WOFF_W2, A, NN, 256, 128, 0, 0.0f, nullptr, MAIN);
    prop_launch<32, 0>(A, x2, b2, off, cs, cw);

    // ---- x3 = relu(prop(x2@W3)+b3)  (64) ----
    gemm(x2, wt + WOFF_W3, A, NN, 128, 64, 0, 0.0f, nullptr, MAIN);
    prop_launch<16, 0>(A, B, b3, off, cs, cw);

    // ---- x3 = relu(prop(x3@W4)+b4)  (32) ----
    gemm(B, wt + WOFF_W4, A, NN, 64, 32, 0, 0.0f, nullptr, MAIN);
    prop_launch<8, 0>(A, B, b4, off, cs, cw);

    // ---- GATv2 (128); xl=C (main), xr=A (side) — fused flash-softmax ----
    cudaEventRecord(s_ev2, MAIN);
    cudaStreamWaitEvent(s_side, s_ev2, 0);
    gemm(B, wt + WOFF_WR, A, NN, 32, 128, 0, 0.0f, nullptr, s_side);
    cudaEventRecord(s_ev3, s_side);
    gemm(B, wt + WOFF_WL, C, NN, 32, 128, 0, 0.0f, nullptr, MAIN);
    cudaStreamWaitEvent(MAIN, s_ev3, 0);
    gat_fused<<<divup((long long)NN * 32, 256), 256>>>(
        (const float4*)C, (const float4*)A, off, cs,
        (const float4*)att, bg, (float4*)D);

    // ---- GCN2 #1 with x0=x2 (128) ----
    prop_launch<32, 1>(D, A, x2, off, cs, cw);
    gemm(A, wt + WOFF_WC1, B, NN, 128, 128, 1, BETA, nullptr, MAIN);

    // ---- x3 = relu(prop(B)@W5 + b5)  (prop commuted to 128-d) ----
    prop_launch<32, 3>(B, A, nullptr, off, cs, cw);
    gemm(A, wt + WOFF_W5, C, NN, 128, 256, 2, 0.0f, b5, MAIN);

    // ---- GCN2 #2 with x0=x1 (256) ----
    prop_launch<64, 1>(C, A, x1, off, cs, cw);
    gemm(A, wt + WOFF_WC2, B, NN, 256, 256, 1, BETA, nullptr, MAIN);

    // ---- out = prop(x3@Wo) + bo ----
    gemm(B, wt + WOFF_WO, A, NN, 256, 128, 0, 0.0f, nullptr, MAIN);
    prop_launch<32, 2>(A, out, bo, off, cs, cw);
}